// round 12
// baseline (speedup 1.0000x reference)
#include <cuda_runtime.h>
#include <cuda_bf16.h>
#include <cuda_fp16.h>
#include <math.h>
#include <stdint.h>

#define VOCAB 32000
#define DMODEL 64
#define NLAYERS 4
#define BB 512
#define SS 1000
#define EPS 1e-5f

__device__ float g_x[BB * SS * DMODEL];
__device__ float g_pe[SS * DMODEL];
__device__ float g_sums[NLAYERS * BB * DMODEL];
__device__ float g_attn[BB * DMODEL];

// ---------------------------------------------------------------------------
__device__ __forceinline__ uint32_t smem_u32(const void* p) {
    uint32_t a;
    asm("{ .reg .u64 t; cvta.to.shared.u64 t, %1; cvt.u32.u64 %0, t; }"
        : "=r"(a) : "l"(p));
    return a;
}

#define LDSM4(r0, r1, r2, r3, addr)                                         \
    asm volatile("ldmatrix.sync.aligned.m8n8.x4.shared.b16 {%0,%1,%2,%3}, [%4];" \
                 : "=r"(r0), "=r"(r1), "=r"(r2), "=r"(r3) : "r"(addr))

#define MMA_BF16(d, a0, a1, a2, a3, b0, b1)                                 \
    asm volatile("mma.sync.aligned.m16n8k16.row.col.f32.bf16.bf16.f32 "     \
                 "{%0,%1,%2,%3}, {%4,%5,%6,%7}, {%8,%9}, {%0,%1,%2,%3};"    \
                 : "+f"((d)[0]), "+f"((d)[1]), "+f"((d)[2]), "+f"((d)[3])   \
                 : "r"(a0), "r"(a1), "r"(a2), "r"(a3), "r"(b0), "r"(b1))

#define MMA_F16(d, a0, a1, a2, a3, b0, b1)                                  \
    asm volatile("mma.sync.aligned.m16n8k16.row.col.f32.f16.f16.f32 "       \
                 "{%0,%1,%2,%3}, {%4,%5,%6,%7}, {%8,%9}, {%0,%1,%2,%3};"    \
                 : "+f"((d)[0]), "+f"((d)[1]), "+f"((d)[2]), "+f"((d)[3])   \
                 : "r"(a0), "r"(a1), "r"(a2), "r"(a3), "r"(b0), "r"(b1))

__device__ __forceinline__ uint32_t pack_hi(float f0, float f1) {
    __nv_bfloat16 h0 = __float2bfloat16_rn(f0);
    __nv_bfloat16 h1 = __float2bfloat16_rn(f1);
    return ((uint32_t)__bfloat16_as_ushort(h1) << 16) | __bfloat16_as_ushort(h0);
}
__device__ __forceinline__ uint32_t pack_lo(float f0, float f1, uint32_t hi) {
    __nv_bfloat16 h0 = __ushort_as_bfloat16((unsigned short)(hi & 0xFFFF));
    __nv_bfloat16 h1 = __ushort_as_bfloat16((unsigned short)(hi >> 16));
    __nv_bfloat16 q0 = __float2bfloat16_rn(f0 - __bfloat162float(h0));
    __nv_bfloat16 q1 = __float2bfloat16_rn(f1 - __bfloat162float(h1));
    return ((uint32_t)__bfloat16_as_ushort(q1) << 16) | __bfloat16_as_ushort(q0);
}
__device__ __forceinline__ float unpack_add(uint32_t hi, uint32_t lo, int half) {
    unsigned short h = half ? (unsigned short)(hi >> 16) : (unsigned short)(hi & 0xFFFF);
    unsigned short l = half ? (unsigned short)(lo >> 16) : (unsigned short)(lo & 0xFFFF);
    return __bfloat162float(__ushort_as_bfloat16(h)) +
           __bfloat162float(__ushort_as_bfloat16(l));
}
__device__ __forceinline__ uint32_t pack_f16(float a, float b) {
    __half2 t = __floats2half2_rn(a, b);
    return *reinterpret_cast<uint32_t*>(&t);
}
__device__ __forceinline__ uint32_t pack_f16_lo(float f0, float f1, uint32_t hi) {
    __half2 h = *reinterpret_cast<__half2*>(&hi);
    float l0 = f0 - __half2float(__low2half(h));
    float l1 = f1 - __half2float(__high2half(h));
    return pack_f16(l0, l1);
}

// swizzled byte offset inside a (rows x 128B) tile: row r, 16B-chunk c (0..7)
__device__ __forceinline__ uint32_t tile_off(uint32_t r, uint32_t c) {
    return r * 128 + ((c ^ (r & 7u)) << 4);
}

// ---------------------------------------------------------------------------
__global__ void k_init() {
    int i = blockIdx.x * blockDim.x + threadIdx.x;
    int n = blockDim.x * gridDim.x;
    for (int idx = i; idx < NLAYERS * BB * DMODEL; idx += n) g_sums[idx] = 0.0f;
    const float c = -0.14391156634610842f;
    for (int idx = i; idx < SS * DMODEL; idx += n) {
        int s = idx >> 6;
        int j = idx & 63;
        float div = expf(c * (float)(j & ~1));
        float ang = (float)s * div;
        g_pe[idx] = (j & 1) ? cosf(ang) : sinf(ang);
    }
}

__global__ __launch_bounds__(256) void k_embed(const int* __restrict__ toks,
                                               const float* __restrict__ emb) {
    int b = blockIdx.y;
    int s0 = blockIdx.x * 128;
    int w = threadIdx.x >> 5, lane = threadIdx.x & 31;
    float acc0 = 0.f, acc1 = 0.f;
    for (int r = w; r < 128; r += 8) {
        int s = s0 + r;
        if (s >= SS) break;
        int tok = toks[b * SS + s];
        float v0 = emb[tok * DMODEL + lane] * 8.0f + g_pe[s * DMODEL + lane];
        float v1 = emb[tok * DMODEL + 32 + lane] * 8.0f + g_pe[s * DMODEL + 32 + lane];
        int row = b * SS + s;
        g_x[row * DMODEL + lane] = v0;
        g_x[row * DMODEL + 32 + lane] = v1;
        acc0 += v0;
        acc1 += v1;
    }
    atomicAdd(&g_sums[0 * BB * DMODEL + b * DMODEL + lane], acc0);
    atomicAdd(&g_sums[0 * BB * DMODEL + b * DMODEL + 32 + lane], acc1);
}

__global__ void k_attn(const float* __restrict__ lin_w,
                       const float* __restrict__ lin_b, int l) {
    __shared__ float avg[DMODEL];
    int b = blockIdx.x, o = threadIdx.x;
    avg[o] = g_sums[l * BB * DMODEL + b * DMODEL + o] * (1.0f / (float)SS);
    __syncthreads();
    const float* W = lin_w + l * DMODEL * DMODEL + o * DMODEL;
    float a = lin_b[l * DMODEL + o];
#pragma unroll
    for (int k = 0; k < DMODEL; k++) a = fmaf(avg[k], W[k], a);
    g_attn[b * DMODEL + o] = a;
}

// ---------------------------------------------------------------------------
// k_layer8: R6 shape (64 rows/CTA, 4 warps x 16 rows) + race fix +
// fp16 2-pass GEMM2 (R10-validated) + mid-kernel W2 load -> 42.8KB smem,
// 5 CTAs/SM = 20 warps/SM.
// ---------------------------------------------------------------------------
#define P_ATTN 0
#define P_B1 64
#define P_B2 128
#define P_G1 192
#define P_N1 256
#define P_G2 320
#define P_N2 384
#define P_OW 448
#define P_OB 576
#define P_SUM 640

#define SM_YH 2816
#define SM_YL (SM_YH + 8192)
#define SM_H  (SM_YL + 8192)
#define SM_WH (SM_H + 8192)
#define SM_WL (SM_WH + 8192)
#define SM_TOTAL (SM_WL + 8192)

// GEMM1: 3-pass split bf16, aH+aL resident, W LDSM shared (R6's gemm64)
__device__ __forceinline__ void gemm1_bf16(float (&d)[8][4], uint32_t yh,
                                           uint32_t yl, uint32_t wh, uint32_t wl,
                                           int wi, int lane) {
    uint32_t aH[16], aL[16];
    uint32_t ar = (uint32_t)(wi * 16) + (lane & 15);
    uint32_t ac = (uint32_t)(lane >> 4);
#pragma unroll
    for (int kt = 0; kt < 4; kt++) {
        uint32_t off = tile_off(ar, kt * 2 + ac);
        LDSM4(aH[4 * kt], aH[4 * kt + 1], aH[4 * kt + 2], aH[4 * kt + 3], yh + off);
        LDSM4(aL[4 * kt], aL[4 * kt + 1], aL[4 * kt + 2], aL[4 * kt + 3], yl + off);
    }
    uint32_t bg = (uint32_t)(lane >> 3);
    uint32_t wr = ((bg & 2u) << 2) | (lane & 7u);
    uint32_t wc = bg & 1u;
#pragma unroll
    for (int ntp = 0; ntp < 4; ntp++)
#pragma unroll
        for (int kt = 0; kt < 4; kt++) {
            uint32_t off = tile_off(ntp * 16 + wr, kt * 2 + wc);
            uint32_t h0, h1, h2, h3;
            LDSM4(h0, h1, h2, h3, wh + off);
            MMA_BF16(d[2 * ntp], aH[4 * kt], aH[4 * kt + 1], aH[4 * kt + 2],
                     aH[4 * kt + 3], h0, h1);
            MMA_BF16(d[2 * ntp + 1], aH[4 * kt], aH[4 * kt + 1], aH[4 * kt + 2],
                     aH[4 * kt + 3], h2, h3);
            MMA_BF16(d[2 * ntp], aL[4 * kt], aL[4 * kt + 1], aL[4 * kt + 2],
                     aL[4 * kt + 3], h0, h1);
            MMA_BF16(d[2 * ntp + 1], aL[4 * kt], aL[4 * kt + 1], aL[4 * kt + 2],
                     aL[4 * kt + 3], h2, h3);
            uint32_t l0, l1, l2, l3;
            LDSM4(l0, l1, l2, l3, wl + off);
            MMA_BF16(d[2 * ntp], aH[4 * kt], aH[4 * kt + 1], aH[4 * kt + 2],
                     aH[4 * kt + 3], l0, l1);
            MMA_BF16(d[2 * ntp + 1], aH[4 * kt], aH[4 * kt + 1], aH[4 * kt + 2],
                     aH[4 * kt + 3], l2, l3);
        }
}

// GEMM2: 2-pass fp16 (h single resident, W2 split fp16)
__device__ __forceinline__ void gemm2_f16(float (&d)[8][4], uint32_t ht,
                                          uint32_t wh, uint32_t wl, int wi,
                                          int lane) {
    uint32_t a[16];
    uint32_t ar = (uint32_t)(wi * 16) + (lane & 15);
    uint32_t ac = (uint32_t)(lane >> 4);
#pragma unroll
    for (int kt = 0; kt < 4; kt++) {
        uint32_t off = tile_off(ar, kt * 2 + ac);
        LDSM4(a[4 * kt], a[4 * kt + 1], a[4 * kt + 2], a[4 * kt + 3], ht + off);
    }
    uint32_t bg = (uint32_t)(lane >> 3);
    uint32_t wr = ((bg & 2u) << 2) | (lane & 7u);
    uint32_t wc = bg & 1u;
#pragma unroll
    for (int ntp = 0; ntp < 4; ntp++)
#pragma unroll
        for (int kt = 0; kt < 4; kt++) {
            uint32_t off = tile_off(ntp * 16 + wr, kt * 2 + wc);
            uint32_t h0, h1, h2, h3;
            LDSM4(h0, h1, h2, h3, wh + off);
            MMA_F16(d[2 * ntp], a[4 * kt], a[4 * kt + 1], a[4 * kt + 2],
                    a[4 * kt + 3], h0, h1);
            MMA_F16(d[2 * ntp + 1], a[4 * kt], a[4 * kt + 1], a[4 * kt + 2],
                    a[4 * kt + 3], h2, h3);
            uint32_t l0, l1, l2, l3;
            LDSM4(l0, l1, l2, l3, wl + off);
            MMA_F16(d[2 * ntp], a[4 * kt], a[4 * kt + 1], a[4 * kt + 2],
                    a[4 * kt + 3], l0, l1);
            MMA_F16(d[2 * ntp + 1], a[4 * kt], a[4 * kt + 1], a[4 * kt + 2],
                    a[4 * kt + 3], l2, l3);
        }
}

__global__ __launch_bounds__(128, 5)
void k_layer8(const float* __restrict__ ff1_w, const float* __restrict__ ff1_b,
              const float* __restrict__ ff2_w, const float* __restrict__ ff2_b,
              const float* __restrict__ n1_g, const float* __restrict__ n1_b,
              const float* __restrict__ n2_g, const float* __restrict__ n2_b,
              const float* __restrict__ out_w, const float* __restrict__ out_b,
              float* __restrict__ out, int l) {
    extern __shared__ char sm[];
    float* P = (float*)sm;
    uint32_t smb = smem_u32(sm);

    int tid = threadIdx.x;
    int wi = tid >> 5;
    int lane = tid & 31;
    int q = lane >> 2, j = lane & 3;
    int b = blockIdx.y;
    int s0 = blockIdx.x * 64;
    int rows_valid = SS - s0;
    if (rows_valid > 64) rows_valid = 64;

    const float* W2g = ff2_w + l * 4096;
    asm volatile("prefetch.global.L2 [%0];" :: "l"(W2g + tid * 32));

    // params
    if (tid < 64) {
        P[P_ATTN + tid] = g_attn[b * DMODEL + tid];
        P[P_B1 + tid] = ff1_b[l * DMODEL + tid];
        P[P_B2 + tid] = ff2_b[l * DMODEL + tid];
        P[P_G1 + tid] = n1_g[l * DMODEL + tid];
        P[P_N1 + tid] = n1_b[l * DMODEL + tid];
        P[P_G2 + tid] = n2_g[l * DMODEL + tid];
        P[P_N2 + tid] = n2_b[l * DMODEL + tid];
        P[P_SUM + tid] = 0.0f;
    }
    P[P_OW + tid] = out_w[tid];
    if (tid < 2) P[P_OB + tid] = out_b[tid];

    // W1 (bf16 split, swizzled) into W region
    const float* W1 = ff1_w + l * 4096;
#pragma unroll
    for (int it = 0; it < 16; it++) {
        int i = tid + it * 128;
        int o = i >> 5, k2 = i & 31;
        uint32_t off = (uint32_t)(o * 128) +
                       ((((uint32_t)(k2 >> 2)) ^ (o & 7u)) << 4) + (k2 & 3) * 4;
        float w0 = W1[o * 64 + k2 * 2], w1 = W1[o * 64 + k2 * 2 + 1];
        uint32_t hi = pack_hi(w0, w1);
        *(uint32_t*)(sm + SM_WH + off) = hi;
        *(uint32_t*)(sm + SM_WL + off) = pack_lo(w0, w1, hi);
    }
    // params written by threads 0-63, read by all warps in LN1 (R9 race fix)
    __syncthreads();

    // LN1: rows r0 = wi*16+q, r1 = r0+8; y split bf16 -> YH/YL
    int r0 = wi * 16 + q, r1 = r0 + 8;
    bool ok0 = (r0 < rows_valid), ok1 = (r1 < rows_valid);
    {
        const float* x0 = g_x + (size_t)(b * SS + s0 + r0) * 64;
        const float* x1 = g_x + (size_t)(b * SS + s0 + r1) * 64;
        float v0[16], v1[16];
        float sm0 = 0.f, sq0 = 0.f, sm1 = 0.f, sq1 = 0.f;
#pragma unroll
        for (int nt = 0; nt < 8; nt++) {
            int c = nt * 8 + 2 * j;
            float2 t0 = ok0 ? *(const float2*)(x0 + c) : make_float2(0.f, 0.f);
            float2 t1 = ok1 ? *(const float2*)(x1 + c) : make_float2(0.f, 0.f);
            float a0 = t0.x + P[P_ATTN + c], a1 = t0.y + P[P_ATTN + c + 1];
            float a2 = t1.x + P[P_ATTN + c], a3 = t1.y + P[P_ATTN + c + 1];
            v0[2 * nt] = a0; v0[2 * nt + 1] = a1;
            v1[2 * nt] = a2; v1[2 * nt + 1] = a3;
            sm0 += a0 + a1; sq0 += a0 * a0 + a1 * a1;
            sm1 += a2 + a3; sq1 += a2 * a2 + a3 * a3;
        }
        sm0 += __shfl_xor_sync(0xffffffffu, sm0, 1);
        sq0 += __shfl_xor_sync(0xffffffffu, sq0, 1);
        sm1 += __shfl_xor_sync(0xffffffffu, sm1, 1);
        sq1 += __shfl_xor_sync(0xffffffffu, sq1, 1);
        sm0 += __shfl_xor_sync(0xffffffffu, sm0, 2);
        sq0 += __shfl_xor_sync(0xffffffffu, sq0, 2);
        sm1 += __shfl_xor_sync(0xffffffffu, sm1, 2);
        sq1 += __shfl_xor_sync(0xffffffffu, sq1, 2);
        float mu0 = sm0 * (1.0f / 64.0f);
        float rs0 = rsqrtf(sq0 * (1.0f / 64.0f) - mu0 * mu0 + EPS);
        float mu1 = sm1 * (1.0f / 64.0f);
        float rs1 = rsqrtf(sq1 * (1.0f / 64.0f) - mu1 * mu1 + EPS);
#pragma unroll
        for (int nt = 0; nt < 8; nt++) {
            int c = nt * 8 + 2 * j;
            float g0 = P[P_G1 + c], g1 = P[P_G1 + c + 1];
            float n0 = P[P_N1 + c], n1 = P[P_N1 + c + 1];
            float y0 = (v0[2 * nt] - mu0) * rs0 * g0 + n0;
            float y1 = (v0[2 * nt + 1] - mu0) * rs0 * g1 + n1;
            float y2 = (v1[2 * nt] - mu1) * rs1 * g0 + n0;
            float y3 = (v1[2 * nt + 1] - mu1) * rs1 * g1 + n1;
            uint32_t hi0 = pack_hi(y0, y1), hi1 = pack_hi(y2, y3);
            uint32_t o0 = tile_off((uint32_t)r0, (uint32_t)nt) + 4 * j;
            uint32_t o1 = tile_off((uint32_t)r1, (uint32_t)nt) + 4 * j;
            *(uint32_t*)(sm + SM_YH + o0) = hi0;
            *(uint32_t*)(sm + SM_YL + o0) = pack_lo(y0, y1, hi0);
            *(uint32_t*)(sm + SM_YH + o1) = hi1;
            *(uint32_t*)(sm + SM_YL + o1) = pack_lo(y2, y3, hi1);
        }
    }
    __syncthreads();

    // GEMM1 (bf16 3-pass)
    float d1[8][4];
#pragma unroll
    for (int n = 0; n < 8; n++)
#pragma unroll
        for (int k = 0; k < 4; k++) d1[n][k] = 0.f;
    gemm1_bf16(d1, smb + SM_YH, smb + SM_YL, smb + SM_WH, smb + SM_WL, wi, lane);
    __syncthreads();  // all W1 reads done before W region overwrite

    // relu -> H (single fp16; warp-local rows)
#pragma unroll
    for (int nt = 0; nt < 8; nt++) {
        int c = nt * 8 + 2 * j;
        float b1a = P[P_B1 + c], b1b = P[P_B1 + c + 1];
        float h0 = fmaxf(d1[nt][0] + b1a, 0.f);
        float h1 = fmaxf(d1[nt][1] + b1b, 0.f);
        float h2 = fmaxf(d1[nt][2] + b1a, 0.f);
        float h3 = fmaxf(d1[nt][3] + b1b, 0.f);
        *(uint32_t*)(sm + SM_H + tile_off((uint32_t)r0, (uint32_t)nt) + 4 * j) =
            pack_f16(h0, h1);
        *(uint32_t*)(sm + SM_H + tile_off((uint32_t)r1, (uint32_t)nt) + 4 * j) =
            pack_f16(h2, h3);
    }

    // W2 (fp16 split) overwrites W region
#pragma unroll
    for (int it = 0; it < 16; it++) {
        int i = tid + it * 128;
        int o = i >> 5, k2 = i & 31;
        uint32_t off = (uint32_t)(o * 128) +
                       ((((uint32_t)(k2 >> 2)) ^ (o & 7u)) << 4) + (k2 & 3) * 4;
        float w0 = W2g[o * 64 + k2 * 2], w1 = W2g[o * 64 + k2 * 2 + 1];
        uint32_t hi = pack_f16(w0, w1);
        *(uint32_t*)(sm + SM_WH + off) = hi;
        *(uint32_t*)(sm + SM_WL + off) = pack_f16_lo(w0, w1, hi);
    }
    __syncthreads();

    // GEMM2 (fp16 2-pass)
    float d2[8][4];
#pragma unroll
    for (int n = 0; n < 8; n++)
#pragma unroll
        for (int k = 0; k < 4; k++) d2[n][k] = 0.f;
    gemm2_f16(d2, smb + SM_H, smb + SM_WH, smb + SM_WL, wi, lane);

    // residual + bias + LN2 + epilogue
    float v0[16], v1[16];
    {
        float sm0 = 0.f, sq0 = 0.f, sm1 = 0.f, sq1 = 0.f;
#pragma unroll
        for (int nt = 0; nt < 8; nt++) {
            int c = nt * 8 + 2 * j;
            uint32_t o0 = tile_off((uint32_t)r0, (uint32_t)nt) + 4 * j;
            uint32_t o1 = tile_off((uint32_t)r1, (uint32_t)nt) + 4 * j;
            uint32_t yh0 = *(const uint32_t*)(sm + SM_YH + o0);
            uint32_t yl0 = *(const uint32_t*)(sm + SM_YL + o0);
            uint32_t yh1 = *(const uint32_t*)(sm + SM_YH + o1);
            uint32_t yl1 = *(const uint32_t*)(sm + SM_YL + o1);
            float b2a = P[P_B2 + c], b2b = P[P_B2 + c + 1];
            float a0 = d2[nt][0] + b2a + unpack_add(yh0, yl0, 0);
            float a1 = d2[nt][1] + b2b + unpack_add(yh0, yl0, 1);
            float a2 = d2[nt][2] + b2a + unpack_add(yh1, yl1, 0);
            float a3 = d2[nt][3] + b2b + unpack_add(yh1, yl1, 1);
            v0[2 * nt] = a0; v0[2 * nt + 1] = a1;
            v1[2 * nt] = a2; v1[2 * nt + 1] = a3;
            sm0 += a0 + a1; sq0 += a0 * a0 + a1 * a1;
            sm1 += a2 + a3; sq1 += a2 * a2 + a3 * a3;
        }
        sm0 += __shfl_xor_sync(0xffffffffu, sm0, 1);
        sq0 += __shfl_xor_sync(0xffffffffu, sq0, 1);
        sm1 += __shfl_xor_sync(0xffffffffu, sm1, 1);
        sq1 += __shfl_xor_sync(0xffffffffu, sq1, 1);
        sm0 += __shfl_xor_sync(0xffffffffu, sm0, 2);
        sq0 += __shfl_xor_sync(0xffffffffu, sq0, 2);
        sm1 += __shfl_xor_sync(0xffffffffu, sm1, 2);
        sq1 += __shfl_xor_sync(0xffffffffu, sq1, 2);
        float mu0 = sm0 * (1.0f / 64.0f);
        float rs0 = rsqrtf(sq0 * (1.0f / 64.0f) - mu0 * mu0 + EPS);
        float mu1 = sm1 * (1.0f / 64.0f);
        float rs1 = rsqrtf(sq1 * (1.0f / 64.0f) - mu1 * mu1 + EPS);
#pragma unroll
        for (int nt = 0; nt < 8; nt++) {
            int c = nt * 8 + 2 * j;
            float g0 = P[P_G2 + c], g1 = P[P_G2 + c + 1];
            float n0 = P[P_N2 + c], n1 = P[P_N2 + c + 1];
            v0[2 * nt] = (v0[2 * nt] - mu0) * rs0 * g0 + n0;
            v0[2 * nt + 1] = (v0[2 * nt + 1] - mu0) * rs0 * g1 + n1;
            v1[2 * nt] = (v1[2 * nt] - mu1) * rs1 * g0 + n0;
            v1[2 * nt + 1] = (v1[2 * nt + 1] - mu1) * rs1 * g1 + n1;
        }
    }

    if (l < NLAYERS - 1) {
        float* x0 = g_x + (size_t)(b * SS + s0 + r0) * 64;
        float* x1 = g_x + (size_t)(b * SS + s0 + r1) * 64;
#pragma unroll
        for (int nt = 0; nt < 8; nt++) {
            int c = nt * 8 + 2 * j;
            if (ok0) *(float2*)(x0 + c) = make_float2(v0[2 * nt], v0[2 * nt + 1]);
            if (ok1) *(float2*)(x1 + c) = make_float2(v1[2 * nt], v1[2 * nt + 1]);
        }
        float s[16];
#pragma unroll
        for (int i = 0; i < 16; i++)
            s[i] = (ok0 ? v0[i] : 0.f) + (ok1 ? v1[i] : 0.f);
#pragma unroll
        for (int i = 0; i < 16; i++) {
            s[i] += __shfl_xor_sync(0xffffffffu, s[i], 4);
            s[i] += __shfl_xor_sync(0xffffffffu, s[i], 8);
            s[i] += __shfl_xor_sync(0xffffffffu, s[i], 16);
        }
        if (q == 0) {
#pragma unroll
            for (int nt = 0; nt < 8; nt++) {
                int c = nt * 8 + 2 * j;
                atomicAdd(&P[P_SUM + c], s[2 * nt]);
                atomicAdd(&P[P_SUM + c + 1], s[2 * nt + 1]);
            }
        }
        __syncthreads();
        if (tid < 64)
            atomicAdd(&g_sums[(l + 1) * BB * DMODEL + b * DMODEL + tid],
                      P[P_SUM + tid]);
    } else {
        float p00 = 0.f, p10 = 0.f, p01 = 0.f, p11 = 0.f;
#pragma unroll
        for (int nt = 0; nt < 8; nt++) {
            int c = nt * 8 + 2 * j;
            float w0 = P[P_OW + c], w1 = P[P_OW + c + 1];
            float u0 = P[P_OW + 64 + c], u1 = P[P_OW + 64 + c + 1];
            p00 = fmaf(v0[2 * nt], w0, fmaf(v0[2 * nt + 1], w1, p00));
            p10 = fmaf(v0[2 * nt], u0, fmaf(v0[2 * nt + 1], u1, p10));
            p01 = fmaf(v1[2 * nt], w0, fmaf(v1[2 * nt + 1], w1, p01));
            p11 = fmaf(v1[2 * nt], u0, fmaf(v1[2 * nt + 1], u1, p11));
        }
        p00 += __shfl_xor_sync(0xffffffffu, p00, 1);
        p10 += __shfl_xor_sync(0xffffffffu, p10, 1);
        p01 += __shfl_xor_sync(0xffffffffu, p01, 1);
        p11 += __shfl_xor_sync(0xffffffffu, p11, 1);
        p00 += __shfl_xor_sync(0xffffffffu, p00, 2);
        p10 += __shfl_xor_sync(0xffffffffu, p10, 2);
        p01 += __shfl_xor_sync(0xffffffffu, p01, 2);
        p11 += __shfl_xor_sync(0xffffffffu, p11, 2);
        if (j == 0) {
            if (ok0)
                *(float2*)(out + (size_t)(b * SS + s0 + r0) * 2) =
                    make_float2(p00 + P[P_OB], p10 + P[P_OB + 1]);
            if (ok1)
                *(float2*)(out + (size_t)(b * SS + s0 + r1) * 2) =
                    make_float2(p01 + P[P_OB], p11 + P[P_OB + 1]);
        }
    }
}

// ---------------------------------------------------------------------------
extern "C" void kernel_launch(void* const* d_in, const int* in_sizes, int n_in,
                              void* d_out, int out_size) {
    const int*   tokens = (const int*)d_in[0];
    const float* emb    = (const float*)d_in[1];
    const float* lin_w  = (const float*)d_in[2];
    const float* lin_b  = (const float*)d_in[3];
    const float* ff1_w  = (const float*)d_in[4];
    const float* ff1_b  = (const float*)d_in[5];
    const float* ff2_w  = (const float*)d_in[6];
    const float* ff2_b  = (const float*)d_in[7];
    const float* n1g    = (const float*)d_in[8];
    const float* n1b    = (const float*)d_in[9];
    const float* n2g    = (const float*)d_in[10];
    const float* n2b    = (const float*)d_in[11];
    const float* ow     = (const float*)d_in[12];
    const float* ob     = (const float*)d_in[13];
    float* out = (float*)d_out;

    cudaFuncSetAttribute(k_layer8, cudaFuncAttributeMaxDynamicSharedMemorySize,
                         SM_TOTAL);

    k_init<<<128, 256>>>();
    k_embed<<<dim3(8, BB), 256>>>(tokens, emb);
    for (int l = 0; l < NLAYERS; l++) {
        k_attn<<<BB, 64>>>(lin_w, lin_b, l);
        k_layer8<<<dim3(16, BB), 128, SM_TOTAL>>>(ff1_w, ff1_b, ff2_w, ff2_b,
                                                  n1g, n1b, n2g, n2b, ow, ob,
                                                  out, l);
    }
}

// round 13
// speedup vs baseline: 1.5270x; 1.5270x over previous
#include <cuda_runtime.h>
#include <cuda_bf16.h>
#include <cuda_fp16.h>
#include <math.h>
#include <stdint.h>

#define VOCAB 32000
#define DMODEL 64
#define NLAYERS 4
#define BB 512
#define SS 1000
#define EPS 1e-5f

__device__ float g_x[BB * SS * DMODEL];
__device__ float g_pe[SS * DMODEL];
__device__ float g_sums[NLAYERS * BB * DMODEL];
__device__ float g_attn[BB * DMODEL];

// ---------------------------------------------------------------------------
__device__ __forceinline__ uint32_t smem_u32(const void* p) {
    uint32_t a;
    asm("{ .reg .u64 t; cvta.to.shared.u64 t, %1; cvt.u32.u64 %0, t; }"
        : "=r"(a) : "l"(p));
    return a;
}

#define LDSM4(r0, r1, r2, r3, addr)                                         \
    asm volatile("ldmatrix.sync.aligned.m8n8.x4.shared.b16 {%0,%1,%2,%3}, [%4];" \
                 : "=r"(r0), "=r"(r1), "=r"(r2), "=r"(r3) : "r"(addr))

#define MMA_BF16(d, a0, a1, a2, a3, b0, b1)                                 \
    asm volatile("mma.sync.aligned.m16n8k16.row.col.f32.bf16.bf16.f32 "     \
                 "{%0,%1,%2,%3}, {%4,%5,%6,%7}, {%8,%9}, {%0,%1,%2,%3};"    \
                 : "+f"((d)[0]), "+f"((d)[1]), "+f"((d)[2]), "+f"((d)[3])   \
                 : "r"(a0), "r"(a1), "r"(a2), "r"(a3), "r"(b0), "r"(b1))

#define MMA_F16(d, a0, a1, a2, a3, b0, b1)                                  \
    asm volatile("mma.sync.aligned.m16n8k16.row.col.f32.f16.f16.f32 "       \
                 "{%0,%1,%2,%3}, {%4,%5,%6,%7}, {%8,%9}, {%0,%1,%2,%3};"    \
                 : "+f"((d)[0]), "+f"((d)[1]), "+f"((d)[2]), "+f"((d)[3])   \
                 : "r"(a0), "r"(a1), "r"(a2), "r"(a3), "r"(b0), "r"(b1))

__device__ __forceinline__ uint32_t pack_hi(float f0, float f1) {
    __nv_bfloat16 h0 = __float2bfloat16_rn(f0);
    __nv_bfloat16 h1 = __float2bfloat16_rn(f1);
    return ((uint32_t)__bfloat16_as_ushort(h1) << 16) | __bfloat16_as_ushort(h0);
}
__device__ __forceinline__ uint32_t pack_lo(float f0, float f1, uint32_t hi) {
    __nv_bfloat16 h0 = __ushort_as_bfloat16((unsigned short)(hi & 0xFFFF));
    __nv_bfloat16 h1 = __ushort_as_bfloat16((unsigned short)(hi >> 16));
    __nv_bfloat16 q0 = __float2bfloat16_rn(f0 - __bfloat162float(h0));
    __nv_bfloat16 q1 = __float2bfloat16_rn(f1 - __bfloat162float(h1));
    return ((uint32_t)__bfloat16_as_ushort(q1) << 16) | __bfloat16_as_ushort(q0);
}
__device__ __forceinline__ float unpack_add(uint32_t hi, uint32_t lo, int half) {
    unsigned short h = half ? (unsigned short)(hi >> 16) : (unsigned short)(hi & 0xFFFF);
    unsigned short l = half ? (unsigned short)(lo >> 16) : (unsigned short)(lo & 0xFFFF);
    return __bfloat162float(__ushort_as_bfloat16(h)) +
           __bfloat162float(__ushort_as_bfloat16(l));
}
__device__ __forceinline__ uint32_t pack_f16(float a, float b) {
    __half2 t = __floats2half2_rn(a, b);
    return *reinterpret_cast<uint32_t*>(&t);
}
__device__ __forceinline__ uint32_t pack_f16_lo(float f0, float f1, uint32_t hi) {
    __half2 h = *reinterpret_cast<__half2*>(&hi);
    float l0 = f0 - __half2float(__low2half(h));
    float l1 = f1 - __half2float(__high2half(h));
    return pack_f16(l0, l1);
}

// swizzled byte offset inside a (rows x 128B) tile: row r, 16B-chunk c (0..7)
__device__ __forceinline__ uint32_t tile_off(uint32_t r, uint32_t c) {
    return r * 128 + ((c ^ (r & 7u)) << 4);
}

// ---------------------------------------------------------------------------
__global__ void k_init() {
    int i = blockIdx.x * blockDim.x + threadIdx.x;
    int n = blockDim.x * gridDim.x;
    for (int idx = i; idx < NLAYERS * BB * DMODEL; idx += n) g_sums[idx] = 0.0f;
    const float c = -0.14391156634610842f;
    for (int idx = i; idx < SS * DMODEL; idx += n) {
        int s = idx >> 6;
        int j = idx & 63;
        float div = expf(c * (float)(j & ~1));
        float ang = (float)s * div;
        g_pe[idx] = (j & 1) ? cosf(ang) : sinf(ang);
    }
}

__global__ __launch_bounds__(256) void k_embed(const int* __restrict__ toks,
                                               const float* __restrict__ emb) {
    int b = blockIdx.y;
    int s0 = blockIdx.x * 128;
    int w = threadIdx.x >> 5, lane = threadIdx.x & 31;
    float acc0 = 0.f, acc1 = 0.f;
    for (int r = w; r < 128; r += 8) {
        int s = s0 + r;
        if (s >= SS) break;
        int tok = toks[b * SS + s];
        float v0 = emb[tok * DMODEL + lane] * 8.0f + g_pe[s * DMODEL + lane];
        float v1 = emb[tok * DMODEL + 32 + lane] * 8.0f + g_pe[s * DMODEL + 32 + lane];
        int row = b * SS + s;
        g_x[row * DMODEL + lane] = v0;
        g_x[row * DMODEL + 32 + lane] = v1;
        acc0 += v0;
        acc1 += v1;
    }
    atomicAdd(&g_sums[0 * BB * DMODEL + b * DMODEL + lane], acc0);
    atomicAdd(&g_sums[0 * BB * DMODEL + b * DMODEL + 32 + lane], acc1);
}

__global__ void k_attn(const float* __restrict__ lin_w,
                       const float* __restrict__ lin_b, int l) {
    __shared__ float avg[DMODEL];
    int b = blockIdx.x, o = threadIdx.x;
    avg[o] = g_sums[l * BB * DMODEL + b * DMODEL + o] * (1.0f / (float)SS);
    __syncthreads();
    const float* W = lin_w + l * DMODEL * DMODEL + o * DMODEL;
    float a = lin_b[l * DMODEL + o];
#pragma unroll
    for (int k = 0; k < DMODEL; k++) a = fmaf(avg[k], W[k], a);
    g_attn[b * DMODEL + o] = a;
}

// ---------------------------------------------------------------------------
// k_layer9: exact R6 skeleton (64 rows/CTA, 4 warps x 16 rows, 4 CTAs/SM,
// BOTH weights preloaded) + race fix + fp16 2-pass GEMM2.
// h (single fp16) overwrites the dead W1H tile after GEMM1.
// smem tiles: YH, YL, W1H(->h), W1L, W2H, W2L = 48KB + params = 50.9KB.
// ---------------------------------------------------------------------------
#define P_ATTN 0
#define P_B1 64
#define P_B2 128
#define P_G1 192
#define P_N1 256
#define P_G2 320
#define P_N2 384
#define P_OW 448
#define P_OB 576
#define P_SUM 640

#define SM_YH 2816
#define SM_YL (SM_YH + 8192)
#define SM_W1H (SM_YL + 8192)   // reused as H (single fp16) after GEMM1
#define SM_W1L (SM_W1H + 8192)
#define SM_W2H (SM_W1L + 8192)
#define SM_W2L (SM_W2H + 8192)
#define SM_TOTAL (SM_W2L + 8192)

// GEMM1: 3-pass split bf16, aH+aL resident, W LDSM shared (R6's gemm64)
__device__ __forceinline__ void gemm1_bf16(float (&d)[8][4], uint32_t yh,
                                           uint32_t yl, uint32_t wh, uint32_t wl,
                                           int wi, int lane) {
    uint32_t aH[16], aL[16];
    uint32_t ar = (uint32_t)(wi * 16) + (lane & 15);
    uint32_t ac = (uint32_t)(lane >> 4);
#pragma unroll
    for (int kt = 0; kt < 4; kt++) {
        uint32_t off = tile_off(ar, kt * 2 + ac);
        LDSM4(aH[4 * kt], aH[4 * kt + 1], aH[4 * kt + 2], aH[4 * kt + 3], yh + off);
        LDSM4(aL[4 * kt], aL[4 * kt + 1], aL[4 * kt + 2], aL[4 * kt + 3], yl + off);
    }
    uint32_t bg = (uint32_t)(lane >> 3);
    uint32_t wr = ((bg & 2u) << 2) | (lane & 7u);
    uint32_t wc = bg & 1u;
#pragma unroll
    for (int ntp = 0; ntp < 4; ntp++)
#pragma unroll
        for (int kt = 0; kt < 4; kt++) {
            uint32_t off = tile_off(ntp * 16 + wr, kt * 2 + wc);
            uint32_t h0, h1, h2, h3;
            LDSM4(h0, h1, h2, h3, wh + off);
            MMA_BF16(d[2 * ntp], aH[4 * kt], aH[4 * kt + 1], aH[4 * kt + 2],
                     aH[4 * kt + 3], h0, h1);
            MMA_BF16(d[2 * ntp + 1], aH[4 * kt], aH[4 * kt + 1], aH[4 * kt + 2],
                     aH[4 * kt + 3], h2, h3);
            MMA_BF16(d[2 * ntp], aL[4 * kt], aL[4 * kt + 1], aL[4 * kt + 2],
                     aL[4 * kt + 3], h0, h1);
            MMA_BF16(d[2 * ntp + 1], aL[4 * kt], aL[4 * kt + 1], aL[4 * kt + 2],
                     aL[4 * kt + 3], h2, h3);
            uint32_t l0, l1, l2, l3;
            LDSM4(l0, l1, l2, l3, wl + off);
            MMA_BF16(d[2 * ntp], aH[4 * kt], aH[4 * kt + 1], aH[4 * kt + 2],
                     aH[4 * kt + 3], l0, l1);
            MMA_BF16(d[2 * ntp + 1], aH[4 * kt], aH[4 * kt + 1], aH[4 * kt + 2],
                     aH[4 * kt + 3], l2, l3);
        }
}

// GEMM2: 2-pass fp16 (h single resident, W2 split fp16)
__device__ __forceinline__ void gemm2_f16(float (&d)[8][4], uint32_t ht,
                                          uint32_t wh, uint32_t wl, int wi,
                                          int lane) {
    uint32_t a[16];
    uint32_t ar = (uint32_t)(wi * 16) + (lane & 15);
    uint32_t ac = (uint32_t)(lane >> 4);
#pragma unroll
    for (int kt = 0; kt < 4; kt++) {
        uint32_t off = tile_off(ar, kt * 2 + ac);
        LDSM4(a[4 * kt], a[4 * kt + 1], a[4 * kt + 2], a[4 * kt + 3], ht + off);
    }
    uint32_t bg = (uint32_t)(lane >> 3);
    uint32_t wr = ((bg & 2u) << 2) | (lane & 7u);
    uint32_t wc = bg & 1u;
#pragma unroll
    for (int ntp = 0; ntp < 4; ntp++)
#pragma unroll
        for (int kt = 0; kt < 4; kt++) {
            uint32_t off = tile_off(ntp * 16 + wr, kt * 2 + wc);
            uint32_t h0, h1, h2, h3;
            LDSM4(h0, h1, h2, h3, wh + off);
            MMA_F16(d[2 * ntp], a[4 * kt], a[4 * kt + 1], a[4 * kt + 2],
                    a[4 * kt + 3], h0, h1);
            MMA_F16(d[2 * ntp + 1], a[4 * kt], a[4 * kt + 1], a[4 * kt + 2],
                    a[4 * kt + 3], h2, h3);
            uint32_t l0, l1, l2, l3;
            LDSM4(l0, l1, l2, l3, wl + off);
            MMA_F16(d[2 * ntp], a[4 * kt], a[4 * kt + 1], a[4 * kt + 2],
                    a[4 * kt + 3], l0, l1);
            MMA_F16(d[2 * ntp + 1], a[4 * kt], a[4 * kt + 1], a[4 * kt + 2],
                    a[4 * kt + 3], l2, l3);
        }
}

__global__ __launch_bounds__(128, 4)
void k_layer9(const float* __restrict__ ff1_w, const float* __restrict__ ff1_b,
              const float* __restrict__ ff2_w, const float* __restrict__ ff2_b,
              const float* __restrict__ n1_g, const float* __restrict__ n1_b,
              const float* __restrict__ n2_g, const float* __restrict__ n2_b,
              const float* __restrict__ out_w, const float* __restrict__ out_b,
              float* __restrict__ out, int l) {
    extern __shared__ char sm[];
    float* P = (float*)sm;
    uint32_t smb = smem_u32(sm);

    int tid = threadIdx.x;
    int wi = tid >> 5;
    int lane = tid & 31;
    int q = lane >> 2, j = lane & 3;
    int b = blockIdx.y;
    int s0 = blockIdx.x * 64;
    int rows_valid = SS - s0;
    if (rows_valid > 64) rows_valid = 64;

    // params
    if (tid < 64) {
        P[P_ATTN + tid] = g_attn[b * DMODEL + tid];
        P[P_B1 + tid] = ff1_b[l * DMODEL + tid];
        P[P_B2 + tid] = ff2_b[l * DMODEL + tid];
        P[P_G1 + tid] = n1_g[l * DMODEL + tid];
        P[P_N1 + tid] = n1_b[l * DMODEL + tid];
        P[P_G2 + tid] = n2_g[l * DMODEL + tid];
        P[P_N2 + tid] = n2_b[l * DMODEL + tid];
        P[P_SUM + tid] = 0.0f;
    }
    P[P_OW + tid] = out_w[tid];
    if (tid < 2) P[P_OB + tid] = out_b[tid];

    // W1 (bf16 split) + W2 (fp16 split), both preloaded (R6 pattern)
    const float* W1 = ff1_w + l * 4096;
    const float* W2 = ff2_w + l * 4096;
#pragma unroll
    for (int it = 0; it < 16; it++) {
        int i = tid + it * 128;
        int o = i >> 5, k2 = i & 31;
        uint32_t off = (uint32_t)(o * 128) +
                       ((((uint32_t)(k2 >> 2)) ^ (o & 7u)) << 4) + (k2 & 3) * 4;
        {
            float w0 = W1[o * 64 + k2 * 2], w1 = W1[o * 64 + k2 * 2 + 1];
            uint32_t hi = pack_hi(w0, w1);
            *(uint32_t*)(sm + SM_W1H + off) = hi;
            *(uint32_t*)(sm + SM_W1L + off) = pack_lo(w0, w1, hi);
        }
        {
            float w0 = W2[o * 64 + k2 * 2], w1 = W2[o * 64 + k2 * 2 + 1];
            uint32_t hi = pack_f16(w0, w1);
            *(uint32_t*)(sm + SM_W2H + off) = hi;
            *(uint32_t*)(sm + SM_W2L + off) = pack_f16_lo(w0, w1, hi);
        }
    }
    // params written by threads 0-63, read by all warps in LN1 (race fix)
    __syncthreads();

    // LN1: rows r0 = wi*16+q, r1 = r0+8; y split bf16 -> YH/YL
    int r0 = wi * 16 + q, r1 = r0 + 8;
    bool ok0 = (r0 < rows_valid), ok1 = (r1 < rows_valid);
    {
        const float* x0 = g_x + (size_t)(b * SS + s0 + r0) * 64;
        const float* x1 = g_x + (size_t)(b * SS + s0 + r1) * 64;
        float v0[16], v1[16];
        float sm0 = 0.f, sq0 = 0.f, sm1 = 0.f, sq1 = 0.f;
#pragma unroll
        for (int nt = 0; nt < 8; nt++) {
            int c = nt * 8 + 2 * j;
            float2 t0 = ok0 ? *(const float2*)(x0 + c) : make_float2(0.f, 0.f);
            float2 t1 = ok1 ? *(const float2*)(x1 + c) : make_float2(0.f, 0.f);
            float a0 = t0.x + P[P_ATTN + c], a1 = t0.y + P[P_ATTN + c + 1];
            float a2 = t1.x + P[P_ATTN + c], a3 = t1.y + P[P_ATTN + c + 1];
            v0[2 * nt] = a0; v0[2 * nt + 1] = a1;
            v1[2 * nt] = a2; v1[2 * nt + 1] = a3;
            sm0 += a0 + a1; sq0 += a0 * a0 + a1 * a1;
            sm1 += a2 + a3; sq1 += a2 * a2 + a3 * a3;
        }
        sm0 += __shfl_xor_sync(0xffffffffu, sm0, 1);
        sq0 += __shfl_xor_sync(0xffffffffu, sq0, 1);
        sm1 += __shfl_xor_sync(0xffffffffu, sm1, 1);
        sq1 += __shfl_xor_sync(0xffffffffu, sq1, 1);
        sm0 += __shfl_xor_sync(0xffffffffu, sm0, 2);
        sq0 += __shfl_xor_sync(0xffffffffu, sq0, 2);
        sm1 += __shfl_xor_sync(0xffffffffu, sm1, 2);
        sq1 += __shfl_xor_sync(0xffffffffu, sq1, 2);
        float mu0 = sm0 * (1.0f / 64.0f);
        float rs0 = rsqrtf(sq0 * (1.0f / 64.0f) - mu0 * mu0 + EPS);
        float mu1 = sm1 * (1.0f / 64.0f);
        float rs1 = rsqrtf(sq1 * (1.0f / 64.0f) - mu1 * mu1 + EPS);
#pragma unroll
        for (int nt = 0; nt < 8; nt++) {
            int c = nt * 8 + 2 * j;
            float g0 = P[P_G1 + c], g1 = P[P_G1 + c + 1];
            float n0 = P[P_N1 + c], n1 = P[P_N1 + c + 1];
            float y0 = (v0[2 * nt] - mu0) * rs0 * g0 + n0;
            float y1 = (v0[2 * nt + 1] - mu0) * rs0 * g1 + n1;
            float y2 = (v1[2 * nt] - mu1) * rs1 * g0 + n0;
            float y3 = (v1[2 * nt + 1] - mu1) * rs1 * g1 + n1;
            uint32_t hi0 = pack_hi(y0, y1), hi1 = pack_hi(y2, y3);
            uint32_t o0 = tile_off((uint32_t)r0, (uint32_t)nt) + 4 * j;
            uint32_t o1 = tile_off((uint32_t)r1, (uint32_t)nt) + 4 * j;
            *(uint32_t*)(sm + SM_YH + o0) = hi0;
            *(uint32_t*)(sm + SM_YL + o0) = pack_lo(y0, y1, hi0);
            *(uint32_t*)(sm + SM_YH + o1) = hi1;
            *(uint32_t*)(sm + SM_YL + o1) = pack_lo(y2, y3, hi1);
        }
    }
    __syncthreads();

    // GEMM1 (bf16 3-pass)
    float d1[8][4];
#pragma unroll
    for (int n = 0; n < 8; n++)
#pragma unroll
        for (int k = 0; k < 4; k++) d1[n][k] = 0.f;
    gemm1_bf16(d1, smb + SM_YH, smb + SM_YL, smb + SM_W1H, smb + SM_W1L, wi, lane);
    __syncthreads();  // all W1H reads done before h overwrites it

    // relu -> h (single fp16) into W1H region (warp-local rows)
#pragma unroll
    for (int nt = 0; nt < 8; nt++) {
        int c = nt * 8 + 2 * j;
        float b1a = P[P_B1 + c], b1b = P[P_B1 + c + 1];
        float h0 = fmaxf(d1[nt][0] + b1a, 0.f);
        float h1 = fmaxf(d1[nt][1] + b1b, 0.f);
        float h2 = fmaxf(d1[nt][2] + b1a, 0.f);
        float h3 = fmaxf(d1[nt][3] + b1b, 0.f);
        *(uint32_t*)(sm + SM_W1H + tile_off((uint32_t)r0, (uint32_t)nt) + 4 * j) =
            pack_f16(h0, h1);
        *(uint32_t*)(sm + SM_W1H + tile_off((uint32_t)r1, (uint32_t)nt) + 4 * j) =
            pack_f16(h2, h3);
    }
    __syncwarp();  // h rows are warp-local; warp-level ordering suffices

    // GEMM2 (fp16 2-pass, A = h in W1H region)
    float d2[8][4];
#pragma unroll
    for (int n = 0; n < 8; n++)
#pragma unroll
        for (int k = 0; k < 4; k++) d2[n][k] = 0.f;
    gemm2_f16(d2, smb + SM_W1H, smb + SM_W2H, smb + SM_W2L, wi, lane);

    // residual + bias + LN2 + epilogue
    float v0[16], v1[16];
    {
        float sm0 = 0.f, sq0 = 0.f, sm1 = 0.f, sq1 = 0.f;
#pragma unroll
        for (int nt = 0; nt < 8; nt++) {
            int c = nt * 8 + 2 * j;
            uint32_t o0 = tile_off((uint32_t)r0, (uint32_t)nt) + 4 * j;
            uint32_t o1 = tile_off((uint32_t)r1, (uint32_t)nt) + 4 * j;
            uint32_t yh0 = *(const uint32_t*)(sm + SM_YH + o0);
            uint32_t yl0 = *(const uint32_t*)(sm + SM_YL + o0);
            uint32_t yh1 = *(const uint32_t*)(sm + SM_YH + o1);
            uint32_t yl1 = *(const uint32_t*)(sm + SM_YL + o1);
            float b2a = P[P_B2 + c], b2b = P[P_B2 + c + 1];
            float a0 = d2[nt][0] + b2a + unpack_add(yh0, yl0, 0);
            float a1 = d2[nt][1] + b2b + unpack_add(yh0, yl0, 1);
            float a2 = d2[nt][2] + b2a + unpack_add(yh1, yl1, 0);
            float a3 = d2[nt][3] + b2b + unpack_add(yh1, yl1, 1);
            v0[2 * nt] = a0; v0[2 * nt + 1] = a1;
            v1[2 * nt] = a2; v1[2 * nt + 1] = a3;
            sm0 += a0 + a1; sq0 += a0 * a0 + a1 * a1;
            sm1 += a2 + a3; sq1 += a2 * a2 + a3 * a3;
        }
        sm0 += __shfl_xor_sync(0xffffffffu, sm0, 1);
        sq0 += __shfl_xor_sync(0xffffffffu, sq0, 1);
        sm1 += __shfl_xor_sync(0xffffffffu, sm1, 1);
        sq1 += __shfl_xor_sync(0xffffffffu, sq1, 1);
        sm0 += __shfl_xor_sync(0xffffffffu, sm0, 2);
        sq0 += __shfl_xor_sync(0xffffffffu, sq0, 2);
        sm1 += __shfl_xor_sync(0xffffffffu, sm1, 2);
        sq1 += __shfl_xor_sync(0xffffffffu, sq1, 2);
        float mu0 = sm0 * (1.0f / 64.0f);
        float rs0 = rsqrtf(sq0 * (1.0f / 64.0f) - mu0 * mu0 + EPS);
        float mu1 = sm1 * (1.0f / 64.0f);
        float rs1 = rsqrtf(sq1 * (1.0f / 64.0f) - mu1 * mu1 + EPS);
#pragma unroll
        for (int nt = 0; nt < 8; nt++) {
            int c = nt * 8 + 2 * j;
            float g0 = P[P_G2 + c], g1 = P[P_G2 + c + 1];
            float n0 = P[P_N2 + c], n1 = P[P_N2 + c + 1];
            v0[2 * nt] = (v0[2 * nt] - mu0) * rs0 * g0 + n0;
            v0[2 * nt + 1] = (v0[2 * nt + 1] - mu0) * rs0 * g1 + n1;
            v1[2 * nt] = (v1[2 * nt] - mu1) * rs1 * g0 + n0;
            v1[2 * nt + 1] = (v1[2 * nt + 1] - mu1) * rs1 * g1 + n1;
        }
    }

    if (l < NLAYERS - 1) {
        float* x0 = g_x + (size_t)(b * SS + s0 + r0) * 64;
        float* x1 = g_x + (size_t)(b * SS + s0 + r1) * 64;
#pragma unroll
        for (int nt = 0; nt < 8; nt++) {
            int c = nt * 8 + 2 * j;
            if (ok0) *(float2*)(x0 + c) = make_float2(v0[2 * nt], v0[2 * nt + 1]);
            if (ok1) *(float2*)(x1 + c) = make_float2(v1[2 * nt], v1[2 * nt + 1]);
        }
        float s[16];
#pragma unroll
        for (int i = 0; i < 16; i++)
            s[i] = (ok0 ? v0[i] : 0.f) + (ok1 ? v1[i] : 0.f);
#pragma unroll
        for (int i = 0; i < 16; i++) {
            s[i] += __shfl_xor_sync(0xffffffffu, s[i], 4);
            s[i] += __shfl_xor_sync(0xffffffffu, s[i], 8);
            s[i] += __shfl_xor_sync(0xffffffffu, s[i], 16);
        }
        if (q == 0) {
#pragma unroll
            for (int nt = 0; nt < 8; nt++) {
                int c = nt * 8 + 2 * j;
                atomicAdd(&P[P_SUM + c], s[2 * nt]);
                atomicAdd(&P[P_SUM + c + 1], s[2 * nt + 1]);
            }
        }
        __syncthreads();
        if (tid < 64)
            atomicAdd(&g_sums[(l + 1) * BB * DMODEL + b * DMODEL + tid],
                      P[P_SUM + tid]);
    } else {
        float p00 = 0.f, p10 = 0.f, p01 = 0.f, p11 = 0.f;
#pragma unroll
        for (int nt = 0; nt < 8; nt++) {
            int c = nt * 8 + 2 * j;
            float w0 = P[P_OW + c], w1 = P[P_OW + c + 1];
            float u0 = P[P_OW + 64 + c], u1 = P[P_OW + 64 + c + 1];
            p00 = fmaf(v0[2 * nt], w0, fmaf(v0[2 * nt + 1], w1, p00));
            p10 = fmaf(v0[2 * nt], u0, fmaf(v0[2 * nt + 1], u1, p10));
            p01 = fmaf(v1[2 * nt], w0, fmaf(v1[2 * nt + 1], w1, p01));
            p11 = fmaf(v1[2 * nt], u0, fmaf(v1[2 * nt + 1], u1, p11));
        }
        p00 += __shfl_xor_sync(0xffffffffu, p00, 1);
        p10 += __shfl_xor_sync(0xffffffffu, p10, 1);
        p01 += __shfl_xor_sync(0xffffffffu, p01, 1);
        p11 += __shfl_xor_sync(0xffffffffu, p11, 1);
        p00 += __shfl_xor_sync(0xffffffffu, p00, 2);
        p10 += __shfl_xor_sync(0xffffffffu, p10, 2);
        p01 += __shfl_xor_sync(0xffffffffu, p01, 2);
        p11 += __shfl_xor_sync(0xffffffffu, p11, 2);
        if (j == 0) {
            if (ok0)
                *(float2*)(out + (size_t)(b * SS + s0 + r0) * 2) =
                    make_float2(p00 + P[P_OB], p10 + P[P_OB + 1]);
            if (ok1)
                *(float2*)(out + (size_t)(b * SS + s0 + r1) * 2) =
                    make_float2(p01 + P[P_OB], p11 + P[P_OB + 1]);
        }
    }
}

// ---------------------------------------------------------------------------
extern "C" void kernel_launch(void* const* d_in, const int* in_sizes, int n_in,
                              void* d_out, int out_size) {
    const int*   tokens = (const int*)d_in[0];
    const float* emb    = (const float*)d_in[1];
    const float* lin_w  = (const float*)d_in[2];
    const float* lin_b  = (const float*)d_in[3];
    const float* ff1_w  = (const float*)d_in[4];
    const float* ff1_b  = (const float*)d_in[5];
    const float* ff2_w  = (const float*)d_in[6];
    const float* ff2_b  = (const float*)d_in[7];
    const float* n1g    = (const float*)d_in[8];
    const float* n1b    = (const float*)d_in[9];
    const float* n2g    = (const float*)d_in[10];
    const float* n2b    = (const float*)d_in[11];
    const float* ow     = (const float*)d_in[12];
    const float* ob     = (const float*)d_in[13];
    float* out = (float*)d_out;

    cudaFuncSetAttribute(k_layer9, cudaFuncAttributeMaxDynamicSharedMemorySize,
                         SM_TOTAL);

    k_init<<<128, 256>>>();
    k_embed<<<dim3(8, BB), 256>>>(tokens, emb);
    for (int l = 0; l < NLAYERS; l++) {
        k_attn<<<BB, 64>>>(lin_w, lin_b, l);
        k_layer9<<<dim3(16, BB), 128, SM_TOTAL>>>(ff1_w, ff1_b, ff2_w, ff2_b,
                                                  n1g, n1b, n2g, n2b, ow, ob,
                                                  out, l);
    }
}

// round 14
// speedup vs baseline: 1.6244x; 1.0638x over previous
#include <cuda_runtime.h>
#include <cuda_bf16.h>
#include <cuda_fp16.h>
#include <math.h>
#include <stdint.h>

#define VOCAB 32000
#define DMODEL 64
#define NLAYERS 4
#define BB 512
#define SS 1000
#define EPS 1e-5f

__device__ float g_x[BB * SS * DMODEL];
__device__ float g_pe[SS * DMODEL];
__device__ float g_sums[NLAYERS * BB * DMODEL];
__device__ float g_attn[BB * DMODEL];

// ---------------------------------------------------------------------------
__device__ __forceinline__ uint32_t smem_u32(const void* p) {
    uint32_t a;
    asm("{ .reg .u64 t; cvta.to.shared.u64 t, %1; cvt.u32.u64 %0, t; }"
        : "=r"(a) : "l"(p));
    return a;
}

#define LDSM4(r0, r1, r2, r3, addr)                                         \
    asm volatile("ldmatrix.sync.aligned.m8n8.x4.shared.b16 {%0,%1,%2,%3}, [%4];" \
                 : "=r"(r0), "=r"(r1), "=r"(r2), "=r"(r3) : "r"(addr))

#define MMA_F16(d, a0, a1, a2, a3, b0, b1)                                  \
    asm volatile("mma.sync.aligned.m16n8k16.row.col.f32.f16.f16.f32 "       \
                 "{%0,%1,%2,%3}, {%4,%5,%6,%7}, {%8,%9}, {%0,%1,%2,%3};"    \
                 : "+f"((d)[0]), "+f"((d)[1]), "+f"((d)[2]), "+f"((d)[3])   \
                 : "r"(a0), "r"(a1), "r"(a2), "r"(a3), "r"(b0), "r"(b1))

__device__ __forceinline__ uint32_t pack_f16(float a, float b) {
    __half2 t = __floats2half2_rn(a, b);
    return *reinterpret_cast<uint32_t*>(&t);
}
__device__ __forceinline__ uint32_t pack_f16_lo(float f0, float f1, uint32_t hi) {
    __half2 h = *reinterpret_cast<__half2*>(&hi);
    float l0 = f0 - __half2float(__low2half(h));
    float l1 = f1 - __half2float(__high2half(h));
    return pack_f16(l0, l1);
}
// reconstruct y = hi + lo from split-fp16 words (22-bit effective mantissa)
__device__ __forceinline__ float unpack_add_f16(uint32_t hi, uint32_t lo, int half) {
    __half2 h = *reinterpret_cast<__half2*>(&hi);
    __half2 l = *reinterpret_cast<__half2*>(&lo);
    float hv = half ? __half2float(__high2half(h)) : __half2float(__low2half(h));
    float lv = half ? __half2float(__high2half(l)) : __half2float(__low2half(l));
    return hv + lv;
}

// swizzled byte offset inside a (rows x 128B) tile: row r, 16B-chunk c (0..7)
__device__ __forceinline__ uint32_t tile_off(uint32_t r, uint32_t c) {
    return r * 128 + ((c ^ (r & 7u)) << 4);
}

// ---------------------------------------------------------------------------
__global__ void k_init() {
    int i = blockIdx.x * blockDim.x + threadIdx.x;
    int n = blockDim.x * gridDim.x;
    for (int idx = i; idx < NLAYERS * BB * DMODEL; idx += n) g_sums[idx] = 0.0f;
    const float c = -0.14391156634610842f;
    for (int idx = i; idx < SS * DMODEL; idx += n) {
        int s = idx >> 6;
        int j = idx & 63;
        float div = expf(c * (float)(j & ~1));
        float ang = (float)s * div;
        g_pe[idx] = (j & 1) ? cosf(ang) : sinf(ang);
    }
}

__global__ __launch_bounds__(256) void k_embed(const int* __restrict__ toks,
                                               const float* __restrict__ emb) {
    int b = blockIdx.y;
    int s0 = blockIdx.x * 128;
    int w = threadIdx.x >> 5, lane = threadIdx.x & 31;
    float acc0 = 0.f, acc1 = 0.f;
    for (int r = w; r < 128; r += 8) {
        int s = s0 + r;
        if (s >= SS) break;
        int tok = toks[b * SS + s];
        float v0 = emb[tok * DMODEL + lane] * 8.0f + g_pe[s * DMODEL + lane];
        float v1 = emb[tok * DMODEL + 32 + lane] * 8.0f + g_pe[s * DMODEL + 32 + lane];
        int row = b * SS + s;
        g_x[row * DMODEL + lane] = v0;
        g_x[row * DMODEL + 32 + lane] = v1;
        acc0 += v0;
        acc1 += v1;
    }
    atomicAdd(&g_sums[0 * BB * DMODEL + b * DMODEL + lane], acc0);
    atomicAdd(&g_sums[0 * BB * DMODEL + b * DMODEL + 32 + lane], acc1);
}

__global__ void k_attn(const float* __restrict__ lin_w,
                       const float* __restrict__ lin_b, int l) {
    __shared__ float avg[DMODEL];
    int b = blockIdx.x, o = threadIdx.x;
    avg[o] = g_sums[l * BB * DMODEL + b * DMODEL + o] * (1.0f / (float)SS);
    __syncthreads();
    const float* W = lin_w + l * DMODEL * DMODEL + o * DMODEL;
    float a = lin_b[l * DMODEL + o];
#pragma unroll
    for (int k = 0; k < DMODEL; k++) a = fmaf(avg[k], W[k], a);
    g_attn[b * DMODEL + o] = a;
}

// ---------------------------------------------------------------------------
// k_layer10: R13 skeleton; BOTH GEMMs now fp16 2-pass (A single fp16, W split
// fp16). y stored split-fp16 (residual reconstructed to 22-bit mantissa).
// h (single fp16) overwrites dead W1H after GEMM1. 50.9KB smem, 4 CTAs/SM.
// ---------------------------------------------------------------------------
#define P_ATTN 0
#define P_B1 64
#define P_B2 128
#define P_G1 192
#define P_N1 256
#define P_G2 320
#define P_N2 384
#define P_OW 448
#define P_OB 576
#define P_SUM 640

#define SM_YH 2816
#define SM_YL (SM_YH + 8192)
#define SM_W1H (SM_YL + 8192)   // reused as H (single fp16) after GEMM1
#define SM_W1L (SM_W1H + 8192)
#define SM_W2H (SM_W1L + 8192)
#define SM_W2L (SM_W2H + 8192)
#define SM_TOTAL (SM_W2L + 8192)

// fp16 2-pass GEMM: D = A(single fp16) @ (Wh + Wl)^T, K=64
__device__ __forceinline__ void gemm_f16(float (&d)[8][4], uint32_t at,
                                         uint32_t wh, uint32_t wl, int wi,
                                         int lane) {
    uint32_t a[16];
    uint32_t ar = (uint32_t)(wi * 16) + (lane & 15);
    uint32_t ac = (uint32_t)(lane >> 4);
#pragma unroll
    for (int kt = 0; kt < 4; kt++) {
        uint32_t off = tile_off(ar, kt * 2 + ac);
        LDSM4(a[4 * kt], a[4 * kt + 1], a[4 * kt + 2], a[4 * kt + 3], at + off);
    }
    uint32_t bg = (uint32_t)(lane >> 3);
    uint32_t wr = ((bg & 2u) << 2) | (lane & 7u);
    uint32_t wc = bg & 1u;
#pragma unroll
    for (int ntp = 0; ntp < 4; ntp++)
#pragma unroll
        for (int kt = 0; kt < 4; kt++) {
            uint32_t off = tile_off(ntp * 16 + wr, kt * 2 + wc);
            uint32_t h0, h1, h2, h3;
            LDSM4(h0, h1, h2, h3, wh + off);
            MMA_F16(d[2 * ntp], a[4 * kt], a[4 * kt + 1], a[4 * kt + 2],
                    a[4 * kt + 3], h0, h1);
            MMA_F16(d[2 * ntp + 1], a[4 * kt], a[4 * kt + 1], a[4 * kt + 2],
                    a[4 * kt + 3], h2, h3);
            uint32_t l0, l1, l2, l3;
            LDSM4(l0, l1, l2, l3, wl + off);
            MMA_F16(d[2 * ntp], a[4 * kt], a[4 * kt + 1], a[4 * kt + 2],
                    a[4 * kt + 3], l0, l1);
            MMA_F16(d[2 * ntp + 1], a[4 * kt], a[4 * kt + 1], a[4 * kt + 2],
                    a[4 * kt + 3], l2, l3);
        }
}

__global__ __launch_bounds__(128, 4)
void k_layer10(const float* __restrict__ ff1_w, const float* __restrict__ ff1_b,
               const float* __restrict__ ff2_w, const float* __restrict__ ff2_b,
               const float* __restrict__ n1_g, const float* __restrict__ n1_b,
               const float* __restrict__ n2_g, const float* __restrict__ n2_b,
               const float* __restrict__ out_w, const float* __restrict__ out_b,
               float* __restrict__ out, int l) {
    extern __shared__ char sm[];
    float* P = (float*)sm;
    uint32_t smb = smem_u32(sm);

    int tid = threadIdx.x;
    int wi = tid >> 5;
    int lane = tid & 31;
    int q = lane >> 2, j = lane & 3;
    int b = blockIdx.y;
    int s0 = blockIdx.x * 64;
    int rows_valid = SS - s0;
    if (rows_valid > 64) rows_valid = 64;

    // params
    if (tid < 64) {
        P[P_ATTN + tid] = g_attn[b * DMODEL + tid];
        P[P_B1 + tid] = ff1_b[l * DMODEL + tid];
        P[P_B2 + tid] = ff2_b[l * DMODEL + tid];
        P[P_G1 + tid] = n1_g[l * DMODEL + tid];
        P[P_N1 + tid] = n1_b[l * DMODEL + tid];
        P[P_G2 + tid] = n2_g[l * DMODEL + tid];
        P[P_N2 + tid] = n2_b[l * DMODEL + tid];
        P[P_SUM + tid] = 0.0f;
    }
    P[P_OW + tid] = out_w[tid];
    if (tid < 2) P[P_OB + tid] = out_b[tid];

    // W1 + W2 (both split fp16, swizzled), both preloaded
    const float* W1 = ff1_w + l * 4096;
    const float* W2 = ff2_w + l * 4096;
#pragma unroll
    for (int it = 0; it < 16; it++) {
        int i = tid + it * 128;
        int o = i >> 5, k2 = i & 31;
        uint32_t off = (uint32_t)(o * 128) +
                       ((((uint32_t)(k2 >> 2)) ^ (o & 7u)) << 4) + (k2 & 3) * 4;
        {
            float w0 = W1[o * 64 + k2 * 2], w1 = W1[o * 64 + k2 * 2 + 1];
            uint32_t hi = pack_f16(w0, w1);
            *(uint32_t*)(sm + SM_W1H + off) = hi;
            *(uint32_t*)(sm + SM_W1L + off) = pack_f16_lo(w0, w1, hi);
        }
        {
            float w0 = W2[o * 64 + k2 * 2], w1 = W2[o * 64 + k2 * 2 + 1];
            uint32_t hi = pack_f16(w0, w1);
            *(uint32_t*)(sm + SM_W2H + off) = hi;
            *(uint32_t*)(sm + SM_W2L + off) = pack_f16_lo(w0, w1, hi);
        }
    }
    // params written by threads 0-63, read by all warps in LN1 (race fix)
    __syncthreads();

    // LN1: rows r0 = wi*16+q, r1 = r0+8; y split fp16 -> YH/YL
    int r0 = wi * 16 + q, r1 = r0 + 8;
    bool ok0 = (r0 < rows_valid), ok1 = (r1 < rows_valid);
    {
        const float* x0 = g_x + (size_t)(b * SS + s0 + r0) * 64;
        const float* x1 = g_x + (size_t)(b * SS + s0 + r1) * 64;
        float v0[16], v1[16];
        float sm0 = 0.f, sq0 = 0.f, sm1 = 0.f, sq1 = 0.f;
#pragma unroll
        for (int nt = 0; nt < 8; nt++) {
            int c = nt * 8 + 2 * j;
            float2 t0 = ok0 ? *(const float2*)(x0 + c) : make_float2(0.f, 0.f);
            float2 t1 = ok1 ? *(const float2*)(x1 + c) : make_float2(0.f, 0.f);
            float a0 = t0.x + P[P_ATTN + c], a1 = t0.y + P[P_ATTN + c + 1];
            float a2 = t1.x + P[P_ATTN + c], a3 = t1.y + P[P_ATTN + c + 1];
            v0[2 * nt] = a0; v0[2 * nt + 1] = a1;
            v1[2 * nt] = a2; v1[2 * nt + 1] = a3;
            sm0 += a0 + a1; sq0 += a0 * a0 + a1 * a1;
            sm1 += a2 + a3; sq1 += a2 * a2 + a3 * a3;
        }
        sm0 += __shfl_xor_sync(0xffffffffu, sm0, 1);
        sq0 += __shfl_xor_sync(0xffffffffu, sq0, 1);
        sm1 += __shfl_xor_sync(0xffffffffu, sm1, 1);
        sq1 += __shfl_xor_sync(0xffffffffu, sq1, 1);
        sm0 += __shfl_xor_sync(0xffffffffu, sm0, 2);
        sq0 += __shfl_xor_sync(0xffffffffu, sq0, 2);
        sm1 += __shfl_xor_sync(0xffffffffu, sm1, 2);
        sq1 += __shfl_xor_sync(0xffffffffu, sq1, 2);
        float mu0 = sm0 * (1.0f / 64.0f);
        float rs0 = rsqrtf(sq0 * (1.0f / 64.0f) - mu0 * mu0 + EPS);
        float mu1 = sm1 * (1.0f / 64.0f);
        float rs1 = rsqrtf(sq1 * (1.0f / 64.0f) - mu1 * mu1 + EPS);
#pragma unroll
        for (int nt = 0; nt < 8; nt++) {
            int c = nt * 8 + 2 * j;
            float g0 = P[P_G1 + c], g1 = P[P_G1 + c + 1];
            float n0 = P[P_N1 + c], n1 = P[P_N1 + c + 1];
            float y0 = (v0[2 * nt] - mu0) * rs0 * g0 + n0;
            float y1 = (v0[2 * nt + 1] - mu0) * rs0 * g1 + n1;
            float y2 = (v1[2 * nt] - mu1) * rs1 * g0 + n0;
            float y3 = (v1[2 * nt + 1] - mu1) * rs1 * g1 + n1;
            uint32_t hi0 = pack_f16(y0, y1), hi1 = pack_f16(y2, y3);
            uint32_t o0 = tile_off((uint32_t)r0, (uint32_t)nt) + 4 * j;
            uint32_t o1 = tile_off((uint32_t)r1, (uint32_t)nt) + 4 * j;
            *(uint32_t*)(sm + SM_YH + o0) = hi0;
            *(uint32_t*)(sm + SM_YL + o0) = pack_f16_lo(y0, y1, hi0);
            *(uint32_t*)(sm + SM_YH + o1) = hi1;
            *(uint32_t*)(sm + SM_YL + o1) = pack_f16_lo(y2, y3, hi1);
        }
    }
    // A-tile rows are warp-local (written+read by same warp); W tiles are
    // covered by the barrier above -> warp-level ordering suffices here.
    __syncwarp();

    // GEMM1 (fp16 2-pass, A = yH single fp16)
    float d1[8][4];
#pragma unroll
    for (int n = 0; n < 8; n++)
#pragma unroll
        for (int k = 0; k < 4; k++) d1[n][k] = 0.f;
    gemm_f16(d1, smb + SM_YH, smb + SM_W1H, smb + SM_W1L, wi, lane);
    __syncthreads();  // all warps' W1H reads done before h overwrites it

    // relu -> h (single fp16) into W1H region (warp-local rows)
#pragma unroll
    for (int nt = 0; nt < 8; nt++) {
        int c = nt * 8 + 2 * j;
        float b1a = P[P_B1 + c], b1b = P[P_B1 + c + 1];
        float h0 = fmaxf(d1[nt][0] + b1a, 0.f);
        float h1 = fmaxf(d1[nt][1] + b1b, 0.f);
        float h2 = fmaxf(d1[nt][2] + b1a, 0.f);
        float h3 = fmaxf(d1[nt][3] + b1b, 0.f);
        *(uint32_t*)(sm + SM_W1H + tile_off((uint32_t)r0, (uint32_t)nt) + 4 * j) =
            pack_f16(h0, h1);
        *(uint32_t*)(sm + SM_W1H + tile_off((uint32_t)r1, (uint32_t)nt) + 4 * j) =
            pack_f16(h2, h3);
    }
    __syncwarp();  // h rows are warp-local

    // GEMM2 (fp16 2-pass, A = h in W1H region)
    float d2[8][4];
#pragma unroll
    for (int n = 0; n < 8; n++)
#pragma unroll
        for (int k = 0; k < 4; k++) d2[n][k] = 0.f;
    gemm_f16(d2, smb + SM_W1H, smb + SM_W2H, smb + SM_W2L, wi, lane);

    // residual (split-fp16 reconstruct) + bias + LN2 + epilogue
    float v0[16], v1[16];
    {
        float sm0 = 0.f, sq0 = 0.f, sm1 = 0.f, sq1 = 0.f;
#pragma unroll
        for (int nt = 0; nt < 8; nt++) {
            int c = nt * 8 + 2 * j;
            uint32_t o0 = tile_off((uint32_t)r0, (uint32_t)nt) + 4 * j;
            uint32_t o1 = tile_off((uint32_t)r1, (uint32_t)nt) + 4 * j;
            uint32_t yh0 = *(const uint32_t*)(sm + SM_YH + o0);
            uint32_t yl0 = *(const uint32_t*)(sm + SM_YL + o0);
            uint32_t yh1 = *(const uint32_t*)(sm + SM_YH + o1);
            uint32_t yl1 = *(const uint32_t*)(sm + SM_YL + o1);
            float b2a = P[P_B2 + c], b2b = P[P_B2 + c + 1];
            float a0 = d2[nt][0] + b2a + unpack_add_f16(yh0, yl0, 0);
            float a1 = d2[nt][1] + b2b + unpack_add_f16(yh0, yl0, 1);
            float a2 = d2[nt][2] + b2a + unpack_add_f16(yh1, yl1, 0);
            float a3 = d2[nt][3] + b2b + unpack_add_f16(yh1, yl1, 1);
            v0[2 * nt] = a0; v0[2 * nt + 1] = a1;
            v1[2 * nt] = a2; v1[2 * nt + 1] = a3;
            sm0 += a0 + a1; sq0 += a0 * a0 + a1 * a1;
            sm1 += a2 + a3; sq1 += a2 * a2 + a3 * a3;
        }
        sm0 += __shfl_xor_sync(0xffffffffu, sm0, 1);
        sq0 += __shfl_xor_sync(0xffffffffu, sq0, 1);
        sm1 += __shfl_xor_sync(0xffffffffu, sm1, 1);
        sq1 += __shfl_xor_sync(0xffffffffu, sq1, 1);
        sm0 += __shfl_xor_sync(0xffffffffu, sm0, 2);
        sq0 += __shfl_xor_sync(0xffffffffu, sq0, 2);
        sm1 += __shfl_xor_sync(0xffffffffu, sm1, 2);
        sq1 += __shfl_xor_sync(0xffffffffu, sq1, 2);
        float mu0 = sm0 * (1.0f / 64.0f);
        float rs0 = rsqrtf(sq0 * (1.0f / 64.0f) - mu0 * mu0 + EPS);
        float mu1 = sm1 * (1.0f / 64.0f);
        float rs1 = rsqrtf(sq1 * (1.0f / 64.0f) - mu1 * mu1 + EPS);
#pragma unroll
        for (int nt = 0; nt < 8; nt++) {
            int c = nt * 8 + 2 * j;
            float g0 = P[P_G2 + c], g1 = P[P_G2 + c + 1];
            float n0 = P[P_N2 + c], n1 = P[P_N2 + c + 1];
            v0[2 * nt] = (v0[2 * nt] - mu0) * rs0 * g0 + n0;
            v0[2 * nt + 1] = (v0[2 * nt + 1] - mu0) * rs0 * g1 + n1;
            v1[2 * nt] = (v1[2 * nt] - mu1) * rs1 * g0 + n0;
            v1[2 * nt + 1] = (v1[2 * nt + 1] - mu1) * rs1 * g1 + n1;
        }
    }

    if (l < NLAYERS - 1) {
        float* x0 = g_x + (size_t)(b * SS + s0 + r0) * 64;
        float* x1 = g_x + (size_t)(b * SS + s0 + r1) * 64;
#pragma unroll
        for (int nt = 0; nt < 8; nt++) {
            int c = nt * 8 + 2 * j;
            if (ok0) *(float2*)(x0 + c) = make_float2(v0[2 * nt], v0[2 * nt + 1]);
            if (ok1) *(float2*)(x1 + c) = make_float2(v1[2 * nt], v1[2 * nt + 1]);
        }
        float s[16];
#pragma unroll
        for (int i = 0; i < 16; i++)
            s[i] = (ok0 ? v0[i] : 0.f) + (ok1 ? v1[i] : 0.f);
#pragma unroll
        for (int i = 0; i < 16; i++) {
            s[i] += __shfl_xor_sync(0xffffffffu, s[i], 4);
            s[i] += __shfl_xor_sync(0xffffffffu, s[i], 8);
            s[i] += __shfl_xor_sync(0xffffffffu, s[i], 16);
        }
        if (q == 0) {
#pragma unroll
            for (int nt = 0; nt < 8; nt++) {
                int c = nt * 8 + 2 * j;
                atomicAdd(&P[P_SUM + c], s[2 * nt]);
                atomicAdd(&P[P_SUM + c + 1], s[2 * nt + 1]);
            }
        }
        __syncthreads();
        if (tid < 64)
            atomicAdd(&g_sums[(l + 1) * BB * DMODEL + b * DMODEL + tid],
                      P[P_SUM + tid]);
    } else {
        float p00 = 0.f, p10 = 0.f, p01 = 0.f, p11 = 0.f;
#pragma unroll
        for (int nt = 0; nt < 8; nt++) {
            int c = nt * 8 + 2 * j;
            float w0 = P[P_OW + c], w1 = P[P_OW + c + 1];
            float u0 = P[P_OW + 64 + c], u1 = P[P_OW + 64 + c + 1];
            p00 = fmaf(v0[2 * nt], w0, fmaf(v0[2 * nt + 1], w1, p00));
            p10 = fmaf(v0[2 * nt], u0, fmaf(v0[2 * nt + 1], u1, p10));
            p01 = fmaf(v1[2 * nt], w0, fmaf(v1[2 * nt + 1], w1, p01));
            p11 = fmaf(v1[2 * nt], u0, fmaf(v1[2 * nt + 1], u1, p11));
        }
        p00 += __shfl_xor_sync(0xffffffffu, p00, 1);
        p10 += __shfl_xor_sync(0xffffffffu, p10, 1);
        p01 += __shfl_xor_sync(0xffffffffu, p01, 1);
        p11 += __shfl_xor_sync(0xffffffffu, p11, 1);
        p00 += __shfl_xor_sync(0xffffffffu, p00, 2);
        p10 += __shfl_xor_sync(0xffffffffu, p10, 2);
        p01 += __shfl_xor_sync(0xffffffffu, p01, 2);
        p11 += __shfl_xor_sync(0xffffffffu, p11, 2);
        if (j == 0) {
            if (ok0)
                *(float2*)(out + (size_t)(b * SS + s0 + r0) * 2) =
                    make_float2(p00 + P[P_OB], p10 + P[P_OB + 1]);
            if (ok1)
                *(float2*)(out + (size_t)(b * SS + s0 + r1) * 2) =
                    make_float2(p01 + P[P_OB], p11 + P[P_OB + 1]);
        }
    }
}

// ---------------------------------------------------------------------------
extern "C" void kernel_launch(void* const* d_in, const int* in_sizes, int n_in,
                              void* d_out, int out_size) {
    const int*   tokens = (const int*)d_in[0];
    const float* emb    = (const float*)d_in[1];
    const float* lin_w  = (const float*)d_in[2];
    const float* lin_b  = (const float*)d_in[3];
    const float* ff1_w  = (const float*)d_in[4];
    const float* ff1_b  = (const float*)d_in[5];
    const float* ff2_w  = (const float*)d_in[6];
    const float* ff2_b  = (const float*)d_in[7];
    const float* n1g    = (const float*)d_in[8];
    const float* n1b    = (const float*)d_in[9];
    const float* n2g    = (const float*)d_in[10];
    const float* n2b    = (const float*)d_in[11];
    const float* ow     = (const float*)d_in[12];
    const float* ob     = (const float*)d_in[13];
    float* out = (float*)d_out;

    cudaFuncSetAttribute(k_layer10, cudaFuncAttributeMaxDynamicSharedMemorySize,
                         SM_TOTAL);

    k_init<<<128, 256>>>();
    k_embed<<<dim3(8, BB), 256>>>(tokens, emb);
    for (int l = 0; l < NLAYERS; l++) {
        k_attn<<<BB, 64>>>(lin_w, lin_b, l);
        k_layer10<<<dim3(16, BB), 128, SM_TOTAL>>>(ff1_w, ff1_b, ff2_w, ff2_b,
                                                   n1g, n1b, n2g, n2b, ow, ob,
                                                   out, l);
    }
}

// round 15
// speedup vs baseline: 1.9082x; 1.1747x over previous
#include <cuda_runtime.h>
#include <cuda_bf16.h>
#include <cuda_fp16.h>
#include <math.h>
#include <stdint.h>

#define VOCAB 32000
#define DMODEL 64
#define NLAYERS 4
#define BB 512
#define SS 1000
#define EPS 1e-5f

__device__ float g_x[BB * SS * DMODEL];
__device__ float g_pe[SS * DMODEL];
__device__ float g_sums[NLAYERS * BB * DMODEL];
__device__ float g_attn[BB * DMODEL];

// ---------------------------------------------------------------------------
__device__ __forceinline__ uint32_t smem_u32(const void* p) {
    uint32_t a;
    asm("{ .reg .u64 t; cvta.to.shared.u64 t, %1; cvt.u32.u64 %0, t; }"
        : "=r"(a) : "l"(p));
    return a;
}

#define LDSM4(r0, r1, r2, r3, addr)                                         \
    asm volatile("ldmatrix.sync.aligned.m8n8.x4.shared.b16 {%0,%1,%2,%3}, [%4];" \
                 : "=r"(r0), "=r"(r1), "=r"(r2), "=r"(r3) : "r"(addr))

#define MMA_F16(d, a0, a1, a2, a3, b0, b1)                                  \
    asm volatile("mma.sync.aligned.m16n8k16.row.col.f32.f16.f16.f32 "       \
                 "{%0,%1,%2,%3}, {%4,%5,%6,%7}, {%8,%9}, {%0,%1,%2,%3};"    \
                 : "+f"((d)[0]), "+f"((d)[1]), "+f"((d)[2]), "+f"((d)[3])   \
                 : "r"(a0), "r"(a1), "r"(a2), "r"(a3), "r"(b0), "r"(b1))

__device__ __forceinline__ uint32_t pack_f16(float a, float b) {
    __half2 t = __floats2half2_rn(a, b);
    return *reinterpret_cast<uint32_t*>(&t);
}
__device__ __forceinline__ uint32_t pack_f16_lo(float f0, float f1, uint32_t hi) {
    __half2 h = *reinterpret_cast<__half2*>(&hi);
    float l0 = f0 - __half2float(__low2half(h));
    float l1 = f1 - __half2float(__high2half(h));
    return pack_f16(l0, l1);
}
// reconstruct y = hi + lo from split-fp16 words (22-bit effective mantissa)
__device__ __forceinline__ float unpack_add_f16(uint32_t hi, uint32_t lo, int half) {
    __half2 h = *reinterpret_cast<__half2*>(&hi);
    __half2 l = *reinterpret_cast<__half2*>(&lo);
    float hv = half ? __half2float(__high2half(h)) : __half2float(__low2half(h));
    float lv = half ? __half2float(__high2half(l)) : __half2float(__low2half(l));
    return hv + lv;
}

// swizzled byte offset inside a (rows x 128B) tile: row r, 16B-chunk c (0..7)
__device__ __forceinline__ uint32_t tile_off(uint32_t r, uint32_t c) {
    return r * 128 + ((c ^ (r & 7u)) << 4);
}

// ---------------------------------------------------------------------------
__global__ void k_init() {
    int i = blockIdx.x * blockDim.x + threadIdx.x;
    int n = blockDim.x * gridDim.x;
    for (int idx = i; idx < NLAYERS * BB * DMODEL; idx += n) g_sums[idx] = 0.0f;
    const float c = -0.14391156634610842f;
    for (int idx = i; idx < SS * DMODEL; idx += n) {
        int s = idx >> 6;
        int j = idx & 63;
        float div = expf(c * (float)(j & ~1));
        float ang = (float)s * div;
        g_pe[idx] = (j & 1) ? cosf(ang) : sinf(ang);
    }
}

__global__ __launch_bounds__(256) void k_embed(const int* __restrict__ toks,
                                               const float* __restrict__ emb) {
    int b = blockIdx.y;
    int s0 = blockIdx.x * 128;
    int w = threadIdx.x >> 5, lane = threadIdx.x & 31;
    float acc0 = 0.f, acc1 = 0.f;
    for (int r = w; r < 128; r += 8) {
        int s = s0 + r;
        if (s >= SS) break;
        int tok = toks[b * SS + s];
        float v0 = emb[tok * DMODEL + lane] * 8.0f + g_pe[s * DMODEL + lane];
        float v1 = emb[tok * DMODEL + 32 + lane] * 8.0f + g_pe[s * DMODEL + 32 + lane];
        int row = b * SS + s;
        g_x[row * DMODEL + lane] = v0;
        g_x[row * DMODEL + 32 + lane] = v1;
        acc0 += v0;
        acc1 += v1;
    }
    atomicAdd(&g_sums[0 * BB * DMODEL + b * DMODEL + lane], acc0);
    atomicAdd(&g_sums[0 * BB * DMODEL + b * DMODEL + 32 + lane], acc1);
}

__global__ void k_attn(const float* __restrict__ lin_w,
                       const float* __restrict__ lin_b, int l) {
    __shared__ float avg[DMODEL];
    int b = blockIdx.x, o = threadIdx.x;
    avg[o] = g_sums[l * BB * DMODEL + b * DMODEL + o] * (1.0f / (float)SS);
    __syncthreads();
    const float* W = lin_w + l * DMODEL * DMODEL + o * DMODEL;
    float a = lin_b[l * DMODEL + o];
#pragma unroll
    for (int k = 0; k < DMODEL; k++) a = fmaf(avg[k], W[k], a);
    g_attn[b * DMODEL + o] = a;
}

// ---------------------------------------------------------------------------
// k_layer11: R14 skeleton; BOTH GEMMs 1-pass fp16 x fp16 (A single, W single).
// Residual y kept split-fp16 (YH+YL) for LN2 accuracy. h overwrites W1H.
// 4 tiles = 32KB + params = 34.8KB smem -> 5 CTAs/SM (launch_bounds caps regs).
// ---------------------------------------------------------------------------
#define P_ATTN 0
#define P_B1 64
#define P_B2 128
#define P_G1 192
#define P_N1 256
#define P_G2 320
#define P_N2 384
#define P_OW 448
#define P_OB 576
#define P_SUM 640

#define SM_YH 2816
#define SM_YL (SM_YH + 8192)
#define SM_W1H (SM_YL + 8192)   // reused as H (single fp16) after GEMM1
#define SM_W2H (SM_W1H + 8192)
#define SM_TOTAL (SM_W2H + 8192)

// fp16 1-pass GEMM: D = A(single fp16) @ W(single fp16)^T, K=64
__device__ __forceinline__ void gemm_f16_1p(float (&d)[8][4], uint32_t at,
                                            uint32_t wt, int wi, int lane) {
    uint32_t a[16];
    uint32_t ar = (uint32_t)(wi * 16) + (lane & 15);
    uint32_t ac = (uint32_t)(lane >> 4);
#pragma unroll
    for (int kt = 0; kt < 4; kt++) {
        uint32_t off = tile_off(ar, kt * 2 + ac);
        LDSM4(a[4 * kt], a[4 * kt + 1], a[4 * kt + 2], a[4 * kt + 3], at + off);
    }
    uint32_t bg = (uint32_t)(lane >> 3);
    uint32_t wr = ((bg & 2u) << 2) | (lane & 7u);
    uint32_t wc = bg & 1u;
#pragma unroll
    for (int ntp = 0; ntp < 4; ntp++)
#pragma unroll
        for (int kt = 0; kt < 4; kt++) {
            uint32_t off = tile_off(ntp * 16 + wr, kt * 2 + wc);
            uint32_t h0, h1, h2, h3;
            LDSM4(h0, h1, h2, h3, wt + off);
            MMA_F16(d[2 * ntp], a[4 * kt], a[4 * kt + 1], a[4 * kt + 2],
                    a[4 * kt + 3], h0, h1);
            MMA_F16(d[2 * ntp + 1], a[4 * kt], a[4 * kt + 1], a[4 * kt + 2],
                    a[4 * kt + 3], h2, h3);
        }
}

__global__ __launch_bounds__(128, 5)
void k_layer11(const float* __restrict__ ff1_w, const float* __restrict__ ff1_b,
               const float* __restrict__ ff2_w, const float* __restrict__ ff2_b,
               const float* __restrict__ n1_g, const float* __restrict__ n1_b,
               const float* __restrict__ n2_g, const float* __restrict__ n2_b,
               const float* __restrict__ out_w, const float* __restrict__ out_b,
               float* __restrict__ out, int l) {
    extern __shared__ char sm[];
    float* P = (float*)sm;
    uint32_t smb = smem_u32(sm);

    int tid = threadIdx.x;
    int wi = tid >> 5;
    int lane = tid & 31;
    int q = lane >> 2, j = lane & 3;
    int b = blockIdx.y;
    int s0 = blockIdx.x * 64;
    int rows_valid = SS - s0;
    if (rows_valid > 64) rows_valid = 64;

    // params
    if (tid < 64) {
        P[P_ATTN + tid] = g_attn[b * DMODEL + tid];
        P[P_B1 + tid] = ff1_b[l * DMODEL + tid];
        P[P_B2 + tid] = ff2_b[l * DMODEL + tid];
        P[P_G1 + tid] = n1_g[l * DMODEL + tid];
        P[P_N1 + tid] = n1_b[l * DMODEL + tid];
        P[P_G2 + tid] = n2_g[l * DMODEL + tid];
        P[P_N2 + tid] = n2_b[l * DMODEL + tid];
        P[P_SUM + tid] = 0.0f;
    }
    P[P_OW + tid] = out_w[tid];
    if (tid < 2) P[P_OB + tid] = out_b[tid];

    // W1 + W2 (single fp16, swizzled), both preloaded
    const float* W1 = ff1_w + l * 4096;
    const float* W2 = ff2_w + l * 4096;
#pragma unroll
    for (int it = 0; it < 16; it++) {
        int i = tid + it * 128;
        int o = i >> 5, k2 = i & 31;
        uint32_t off = (uint32_t)(o * 128) +
                       ((((uint32_t)(k2 >> 2)) ^ (o & 7u)) << 4) + (k2 & 3) * 4;
        *(uint32_t*)(sm + SM_W1H + off) =
            pack_f16(W1[o * 64 + k2 * 2], W1[o * 64 + k2 * 2 + 1]);
        *(uint32_t*)(sm + SM_W2H + off) =
            pack_f16(W2[o * 64 + k2 * 2], W2[o * 64 + k2 * 2 + 1]);
    }
    // params written by threads 0-63, read by all warps in LN1 (race fix)
    __syncthreads();

    // LN1: rows r0 = wi*16+q, r1 = r0+8; y split fp16 -> YH/YL
    int r0 = wi * 16 + q, r1 = r0 + 8;
    bool ok0 = (r0 < rows_valid), ok1 = (r1 < rows_valid);
    {
        const float* x0 = g_x + (size_t)(b * SS + s0 + r0) * 64;
        const float* x1 = g_x + (size_t)(b * SS + s0 + r1) * 64;
        float v0[16], v1[16];
        float sm0 = 0.f, sq0 = 0.f, sm1 = 0.f, sq1 = 0.f;
#pragma unroll
        for (int nt = 0; nt < 8; nt++) {
            int c = nt * 8 + 2 * j;
            float2 t0 = ok0 ? *(const float2*)(x0 + c) : make_float2(0.f, 0.f);
            float2 t1 = ok1 ? *(const float2*)(x1 + c) : make_float2(0.f, 0.f);
            float a0 = t0.x + P[P_ATTN + c], a1 = t0.y + P[P_ATTN + c + 1];
            float a2 = t1.x + P[P_ATTN + c], a3 = t1.y + P[P_ATTN + c + 1];
            v0[2 * nt] = a0; v0[2 * nt + 1] = a1;
            v1[2 * nt] = a2; v1[2 * nt + 1] = a3;
            sm0 += a0 + a1; sq0 += a0 * a0 + a1 * a1;
            sm1 += a2 + a3; sq1 += a2 * a2 + a3 * a3;
        }
        sm0 += __shfl_xor_sync(0xffffffffu, sm0, 1);
        sq0 += __shfl_xor_sync(0xffffffffu, sq0, 1);
        sm1 += __shfl_xor_sync(0xffffffffu, sm1, 1);
        sq1 += __shfl_xor_sync(0xffffffffu, sq1, 1);
        sm0 += __shfl_xor_sync(0xffffffffu, sm0, 2);
        sq0 += __shfl_xor_sync(0xffffffffu, sq0, 2);
        sm1 += __shfl_xor_sync(0xffffffffu, sm1, 2);
        sq1 += __shfl_xor_sync(0xffffffffu, sq1, 2);
        float mu0 = sm0 * (1.0f / 64.0f);
        float rs0 = rsqrtf(sq0 * (1.0f / 64.0f) - mu0 * mu0 + EPS);
        float mu1 = sm1 * (1.0f / 64.0f);
        float rs1 = rsqrtf(sq1 * (1.0f / 64.0f) - mu1 * mu1 + EPS);
#pragma unroll
        for (int nt = 0; nt < 8; nt++) {
            int c = nt * 8 + 2 * j;
            float g0 = P[P_G1 + c], g1 = P[P_G1 + c + 1];
            float n0 = P[P_N1 + c], n1 = P[P_N1 + c + 1];
            float y0 = (v0[2 * nt] - mu0) * rs0 * g0 + n0;
            float y1 = (v0[2 * nt + 1] - mu0) * rs0 * g1 + n1;
            float y2 = (v1[2 * nt] - mu1) * rs1 * g0 + n0;
            float y3 = (v1[2 * nt + 1] - mu1) * rs1 * g1 + n1;
            uint32_t hi0 = pack_f16(y0, y1), hi1 = pack_f16(y2, y3);
            uint32_t o0 = tile_off((uint32_t)r0, (uint32_t)nt) + 4 * j;
            uint32_t o1 = tile_off((uint32_t)r1, (uint32_t)nt) + 4 * j;
            *(uint32_t*)(sm + SM_YH + o0) = hi0;
            *(uint32_t*)(sm + SM_YL + o0) = pack_f16_lo(y0, y1, hi0);
            *(uint32_t*)(sm + SM_YH + o1) = hi1;
            *(uint32_t*)(sm + SM_YL + o1) = pack_f16_lo(y2, y3, hi1);
        }
    }
    // A-tile rows are warp-local; W tiles covered by barrier above
    __syncwarp();

    // GEMM1 (fp16 1-pass, A = yH, W = W1 single)
    float d1[8][4];
#pragma unroll
    for (int n = 0; n < 8; n++)
#pragma unroll
        for (int k = 0; k < 4; k++) d1[n][k] = 0.f;
    gemm_f16_1p(d1, smb + SM_YH, smb + SM_W1H, wi, lane);
    __syncthreads();  // all warps' W1H reads done before h overwrites it

    // relu -> h (single fp16) into W1H region (warp-local rows)
#pragma unroll
    for (int nt = 0; nt < 8; nt++) {
        int c = nt * 8 + 2 * j;
        float b1a = P[P_B1 + c], b1b = P[P_B1 + c + 1];
        float h0 = fmaxf(d1[nt][0] + b1a, 0.f);
        float h1 = fmaxf(d1[nt][1] + b1b, 0.f);
        float h2 = fmaxf(d1[nt][2] + b1a, 0.f);
        float h3 = fmaxf(d1[nt][3] + b1b, 0.f);
        *(uint32_t*)(sm + SM_W1H + tile_off((uint32_t)r0, (uint32_t)nt) + 4 * j) =
            pack_f16(h0, h1);
        *(uint32_t*)(sm + SM_W1H + tile_off((uint32_t)r1, (uint32_t)nt) + 4 * j) =
            pack_f16(h2, h3);
    }
    __syncwarp();  // h rows are warp-local

    // GEMM2 (fp16 1-pass, A = h in W1H region, W = W2 single)
    float d2[8][4];
#pragma unroll
    for (int n = 0; n < 8; n++)
#pragma unroll
        for (int k = 0; k < 4; k++) d2[n][k] = 0.f;
    gemm_f16_1p(d2, smb + SM_W1H, smb + SM_W2H, wi, lane);

    // residual (split-fp16 reconstruct) + bias + LN2 + epilogue
    float v0[16], v1[16];
    {
        float sm0 = 0.f, sq0 = 0.f, sm1 = 0.f, sq1 = 0.f;
#pragma unroll
        for (int nt = 0; nt < 8; nt++) {
            int c = nt * 8 + 2 * j;
            uint32_t o0 = tile_off((uint32_t)r0, (uint32_t)nt) + 4 * j;
            uint32_t o1 = tile_off((uint32_t)r1, (uint32_t)nt) + 4 * j;
            uint32_t yh0 = *(const uint32_t*)(sm + SM_YH + o0);
            uint32_t yl0 = *(const uint32_t*)(sm + SM_YL + o0);
            uint32_t yh1 = *(const uint32_t*)(sm + SM_YH + o1);
            uint32_t yl1 = *(const uint32_t*)(sm + SM_YL + o1);
            float b2a = P[P_B2 + c], b2b = P[P_B2 + c + 1];
            float a0 = d2[nt][0] + b2a + unpack_add_f16(yh0, yl0, 0);
            float a1 = d2[nt][1] + b2b + unpack_add_f16(yh0, yl0, 1);
            float a2 = d2[nt][2] + b2a + unpack_add_f16(yh1, yl1, 0);
            float a3 = d2[nt][3] + b2b + unpack_add_f16(yh1, yl1, 1);
            v0[2 * nt] = a0; v0[2 * nt + 1] = a1;
            v1[2 * nt] = a2; v1[2 * nt + 1] = a3;
            sm0 += a0 + a1; sq0 += a0 * a0 + a1 * a1;
            sm1 += a2 + a3; sq1 += a2 * a2 + a3 * a3;
        }
        sm0 += __shfl_xor_sync(0xffffffffu, sm0, 1);
        sq0 += __shfl_xor_sync(0xffffffffu, sq0, 1);
        sm1 += __shfl_xor_sync(0xffffffffu, sm1, 1);
        sq1 += __shfl_xor_sync(0xffffffffu, sq1, 1);
        sm0 += __shfl_xor_sync(0xffffffffu, sm0, 2);
        sq0 += __shfl_xor_sync(0xffffffffu, sq0, 2);
        sm1 += __shfl_xor_sync(0xffffffffu, sm1, 2);
        sq1 += __shfl_xor_sync(0xffffffffu, sq1, 2);
        float mu0 = sm0 * (1.0f / 64.0f);
        float rs0 = rsqrtf(sq0 * (1.0f / 64.0f) - mu0 * mu0 + EPS);
        float mu1 = sm1 * (1.0f / 64.0f);
        float rs1 = rsqrtf(sq1 * (1.0f / 64.0f) - mu1 * mu1 + EPS);
#pragma unroll
        for (int nt = 0; nt < 8; nt++) {
            int c = nt * 8 + 2 * j;
            float g0 = P[P_G2 + c], g1 = P[P_G2 + c + 1];
            float n0 = P[P_N2 + c], n1 = P[P_N2 + c + 1];
            v0[2 * nt] = (v0[2 * nt] - mu0) * rs0 * g0 + n0;
            v0[2 * nt + 1] = (v0[2 * nt + 1] - mu0) * rs0 * g1 + n1;
            v1[2 * nt] = (v1[2 * nt] - mu1) * rs1 * g0 + n0;
            v1[2 * nt + 1] = (v1[2 * nt + 1] - mu1) * rs1 * g1 + n1;
        }
    }

    if (l < NLAYERS - 1) {
        float* x0 = g_x + (size_t)(b * SS + s0 + r0) * 64;
        float* x1 = g_x + (size_t)(b * SS + s0 + r1) * 64;
#pragma unroll
        for (int nt = 0; nt < 8; nt++) {
            int c = nt * 8 + 2 * j;
            if (ok0) *(float2*)(x0 + c) = make_float2(v0[2 * nt], v0[2 * nt + 1]);
            if (ok1) *(float2*)(x1 + c) = make_float2(v1[2 * nt], v1[2 * nt + 1]);
        }
        float s[16];
#pragma unroll
        for (int i = 0; i < 16; i++)
            s[i] = (ok0 ? v0[i] : 0.f) + (ok1 ? v1[i] : 0.f);
#pragma unroll
        for (int i = 0; i < 16; i++) {
            s[i] += __shfl_xor_sync(0xffffffffu, s[i], 4);
            s[i] += __shfl_xor_sync(0xffffffffu, s[i], 8);
            s[i] += __shfl_xor_sync(0xffffffffu, s[i], 16);
        }
        if (q == 0) {
#pragma unroll
            for (int nt = 0; nt < 8; nt++) {
                int c = nt * 8 + 2 * j;
                atomicAdd(&P[P_SUM + c], s[2 * nt]);
                atomicAdd(&P[P_SUM + c + 1], s[2 * nt + 1]);
            }
        }
        __syncthreads();
        if (tid < 64)
            atomicAdd(&g_sums[(l + 1) * BB * DMODEL + b * DMODEL + tid],
                      P[P_SUM + tid]);
    } else {
        float p00 = 0.f, p10 = 0.f, p01 = 0.f, p11 = 0.f;
#pragma unroll
        for (int nt = 0; nt < 8; nt++) {
            int c = nt * 8 + 2 * j;
            float w0 = P[P_OW + c], w1 = P[P_OW + c + 1];
            float u0 = P[P_OW + 64 + c], u1 = P[P_OW + 64 + c + 1];
            p00 = fmaf(v0[2 * nt], w0, fmaf(v0[2 * nt + 1], w1, p00));
            p10 = fmaf(v0[2 * nt], u0, fmaf(v0[2 * nt + 1], u1, p10));
            p01 = fmaf(v1[2 * nt], w0, fmaf(v1[2 * nt + 1], w1, p01));
            p11 = fmaf(v1[2 * nt], u0, fmaf(v1[2 * nt + 1], u1, p11));
        }
        p00 += __shfl_xor_sync(0xffffffffu, p00, 1);
        p10 += __shfl_xor_sync(0xffffffffu, p10, 1);
        p01 += __shfl_xor_sync(0xffffffffu, p01, 1);
        p11 += __shfl_xor_sync(0xffffffffu, p11, 1);
        p00 += __shfl_xor_sync(0xffffffffu, p00, 2);
        p10 += __shfl_xor_sync(0xffffffffu, p10, 2);
        p01 += __shfl_xor_sync(0xffffffffu, p01, 2);
        p11 += __shfl_xor_sync(0xffffffffu, p11, 2);
        if (j == 0) {
            if (ok0)
                *(float2*)(out + (size_t)(b * SS + s0 + r0) * 2) =
                    make_float2(p00 + P[P_OB], p10 + P[P_OB + 1]);
            if (ok1)
                *(float2*)(out + (size_t)(b * SS + s0 + r1) * 2) =
                    make_float2(p01 + P[P_OB], p11 + P[P_OB + 1]);
        }
    }
}

// ---------------------------------------------------------------------------
extern "C" void kernel_launch(void* const* d_in, const int* in_sizes, int n_in,
                              void* d_out, int out_size) {
    const int*   tokens = (const int*)d_in[0];
    const float* emb    = (const float*)d_in[1];
    const float* lin_w  = (const float*)d_in[2];
    const float* lin_b  = (const float*)d_in[3];
    const float* ff1_w  = (const float*)d_in[4];
    const float* ff1_b  = (const float*)d_in[5];
    const float* ff2_w  = (const float*)d_in[6];
    const float* ff2_b  = (const float*)d_in[7];
    const float* n1g    = (const float*)d_in[8];
    const float* n1b    = (const float*)d_in[9];
    const float* n2g    = (const float*)d_in[10];
    const float* n2b    = (const float*)d_in[11];
    const float* ow     = (const float*)d_in[12];
    const float* ob     = (const float*)d_in[13];
    float* out = (float*)d_out;

    cudaFuncSetAttribute(k_layer11, cudaFuncAttributeMaxDynamicSharedMemorySize,
                         SM_TOTAL);

    k_init<<<128, 256>>>();
    k_embed<<<dim3(8, BB), 256>>>(tokens, emb);
    for (int l = 0; l < NLAYERS; l++) {
        k_attn<<<BB, 64>>>(lin_w, lin_b, l);
        k_layer11<<<dim3(16, BB), 128, SM_TOTAL>>>(ff1_w, ff1_b, ff2_w, ff2_b,
                                                   n1g, n1b, n2g, n2b, ow, ob,
                                                   out, l);
    }
}

// round 16
// speedup vs baseline: 2.1151x; 1.1084x over previous
#include <cuda_runtime.h>
#include <cuda_bf16.h>
#include <cuda_fp16.h>
#include <math.h>
#include <stdint.h>

#define VOCAB 32000
#define DMODEL 64
#define NLAYERS 4
#define BB 512
#define SS 1000
#define EPS 1e-5f

__device__ float g_x[BB * SS * DMODEL];
__device__ float g_pe[SS * DMODEL];
__device__ float g_sums[NLAYERS * BB * DMODEL];
__device__ float g_attn[BB * DMODEL];

// ---------------------------------------------------------------------------
__device__ __forceinline__ uint32_t smem_u32(const void* p) {
    uint32_t a;
    asm("{ .reg .u64 t; cvta.to.shared.u64 t, %1; cvt.u32.u64 %0, t; }"
        : "=r"(a) : "l"(p));
    return a;
}

#define LDSM4(r0, r1, r2, r3, addr)                                         \
    asm volatile("ldmatrix.sync.aligned.m8n8.x4.shared.b16 {%0,%1,%2,%3}, [%4];" \
                 : "=r"(r0), "=r"(r1), "=r"(r2), "=r"(r3) : "r"(addr))

#define MMA_F16(d, a0, a1, a2, a3, b0, b1)                                  \
    asm volatile("mma.sync.aligned.m16n8k16.row.col.f32.f16.f16.f32 "       \
                 "{%0,%1,%2,%3}, {%4,%5,%6,%7}, {%8,%9}, {%0,%1,%2,%3};"    \
                 : "+f"((d)[0]), "+f"((d)[1]), "+f"((d)[2]), "+f"((d)[3])   \
                 : "r"(a0), "r"(a1), "r"(a2), "r"(a3), "r"(b0), "r"(b1))

__device__ __forceinline__ uint32_t pack_f16(float a, float b) {
    __half2 t = __floats2half2_rn(a, b);
    return *reinterpret_cast<uint32_t*>(&t);
}
__device__ __forceinline__ float2 unpack_f16(uint32_t u) {
    __half2 h = *reinterpret_cast<__half2*>(&u);
    return make_float2(__half2float(__low2half(h)), __half2float(__high2half(h)));
}

// swizzled byte offset inside a (rows x 128B) tile: row r, 16B-chunk c (0..7)
__device__ __forceinline__ uint32_t tile_off(uint32_t r, uint32_t c) {
    return r * 128 + ((c ^ (r & 7u)) << 4);
}

// ---------------------------------------------------------------------------
__global__ void k_init() {
    int i = blockIdx.x * blockDim.x + threadIdx.x;
    int n = blockDim.x * gridDim.x;
    for (int idx = i; idx < NLAYERS * BB * DMODEL; idx += n) g_sums[idx] = 0.0f;
    const float c = -0.14391156634610842f;
    for (int idx = i; idx < SS * DMODEL; idx += n) {
        int s = idx >> 6;
        int j = idx & 63;
        float div = expf(c * (float)(j & ~1));
        float ang = (float)s * div;
        g_pe[idx] = (j & 1) ? cosf(ang) : sinf(ang);
    }
}

__global__ __launch_bounds__(256) void k_embed(const int* __restrict__ toks,
                                               const float* __restrict__ emb) {
    int b = blockIdx.y;
    int s0 = blockIdx.x * 128;
    int w = threadIdx.x >> 5, lane = threadIdx.x & 31;
    float acc0 = 0.f, acc1 = 0.f;
    for (int r = w; r < 128; r += 8) {
        int s = s0 + r;
        if (s >= SS) break;
        int tok = toks[b * SS + s];
        float v0 = emb[tok * DMODEL + lane] * 8.0f + g_pe[s * DMODEL + lane];
        float v1 = emb[tok * DMODEL + 32 + lane] * 8.0f + g_pe[s * DMODEL + 32 + lane];
        int row = b * SS + s;
        g_x[row * DMODEL + lane] = v0;
        g_x[row * DMODEL + 32 + lane] = v1;
        acc0 += v0;
        acc1 += v1;
    }
    atomicAdd(&g_sums[0 * BB * DMODEL + b * DMODEL + lane], acc0);
    atomicAdd(&g_sums[0 * BB * DMODEL + b * DMODEL + 32 + lane], acc1);
}

__global__ void k_attn(const float* __restrict__ lin_w,
                       const float* __restrict__ lin_b, int l) {
    __shared__ float avg[DMODEL];
    int b = blockIdx.x, o = threadIdx.x;
    avg[o] = g_sums[l * BB * DMODEL + b * DMODEL + o] * (1.0f / (float)SS);
    __syncthreads();
    const float* W = lin_w + l * DMODEL * DMODEL + o * DMODEL;
    float a = lin_b[l * DMODEL + o];
#pragma unroll
    for (int k = 0; k < DMODEL; k++) a = fmaf(avg[k], W[k], a);
    g_attn[b * DMODEL + o] = a;
}

// ---------------------------------------------------------------------------
// k_layer12: A-operands live in REGISTERS (D-frag == A-frag layout identity).
// y (LN1 out) packed fp16x2 -> GEMM1 A operand AND residual source.
// relu(d1)+b1 packed fp16x2 -> GEMM2 A operand. No A smem tiles, no A LDSM,
// no mid-kernel barriers. smem = params + W1 + W2 = 18.8KB; 5 CTAs/SM.
// ---------------------------------------------------------------------------
#define P_ATTN 0
#define P_B1 64
#define P_B2 128
#define P_G1 192
#define P_N1 256
#define P_G2 320
#define P_N2 384
#define P_OW 448
#define P_OB 576
#define P_SUM 640

#define SM_W1H 2816
#define SM_W2H (SM_W1H + 8192)
#define SM_TOTAL (SM_W2H + 8192)

// fp16 GEMM with register A: D += A(frags) @ W(smem, single fp16)^T, K=64
__device__ __forceinline__ void gemm_f16_regA(float (&d)[8][4],
                                              const uint32_t (&a)[16],
                                              uint32_t wt, int lane) {
    uint32_t bg = (uint32_t)(lane >> 3);
    uint32_t wr = ((bg & 2u) << 2) | (lane & 7u);
    uint32_t wc = bg & 1u;
#pragma unroll
    for (int ntp = 0; ntp < 4; ntp++)
#pragma unroll
        for (int kt = 0; kt < 4; kt++) {
            uint32_t off = tile_off(ntp * 16 + wr, kt * 2 + wc);
            uint32_t h0, h1, h2, h3;
            LDSM4(h0, h1, h2, h3, wt + off);
            MMA_F16(d[2 * ntp], a[4 * kt], a[4 * kt + 1], a[4 * kt + 2],
                    a[4 * kt + 3], h0, h1);
            MMA_F16(d[2 * ntp + 1], a[4 * kt], a[4 * kt + 1], a[4 * kt + 2],
                    a[4 * kt + 3], h2, h3);
        }
}

__global__ __launch_bounds__(128, 5)
void k_layer12(const float* __restrict__ ff1_w, const float* __restrict__ ff1_b,
               const float* __restrict__ ff2_w, const float* __restrict__ ff2_b,
               const float* __restrict__ n1_g, const float* __restrict__ n1_b,
               const float* __restrict__ n2_g, const float* __restrict__ n2_b,
               const float* __restrict__ out_w, const float* __restrict__ out_b,
               float* __restrict__ out, int l) {
    extern __shared__ char sm[];
    float* P = (float*)sm;
    uint32_t smb = smem_u32(sm);

    int tid = threadIdx.x;
    int wi = tid >> 5;
    int lane = tid & 31;
    int q = lane >> 2, j = lane & 3;
    int b = blockIdx.y;
    int s0 = blockIdx.x * 64;
    int rows_valid = SS - s0;
    if (rows_valid > 64) rows_valid = 64;

    // params
    if (tid < 64) {
        P[P_ATTN + tid] = g_attn[b * DMODEL + tid];
        P[P_B1 + tid] = ff1_b[l * DMODEL + tid];
        P[P_B2 + tid] = ff2_b[l * DMODEL + tid];
        P[P_G1 + tid] = n1_g[l * DMODEL + tid];
        P[P_N1 + tid] = n1_b[l * DMODEL + tid];
        P[P_G2 + tid] = n2_g[l * DMODEL + tid];
        P[P_N2 + tid] = n2_b[l * DMODEL + tid];
        P[P_SUM + tid] = 0.0f;
    }
    P[P_OW + tid] = out_w[tid];
    if (tid < 2) P[P_OB + tid] = out_b[tid];

    // W1 + W2 (single fp16, swizzled), both preloaded
    const float* W1 = ff1_w + l * 4096;
    const float* W2 = ff2_w + l * 4096;
#pragma unroll
    for (int it = 0; it < 16; it++) {
        int i = tid + it * 128;
        int o = i >> 5, k2 = i & 31;
        uint32_t off = (uint32_t)(o * 128) +
                       ((((uint32_t)(k2 >> 2)) ^ (o & 7u)) << 4) + (k2 & 3) * 4;
        *(uint32_t*)(sm + SM_W1H + off) =
            pack_f16(W1[o * 64 + k2 * 2], W1[o * 64 + k2 * 2 + 1]);
        *(uint32_t*)(sm + SM_W2H + off) =
            pack_f16(W2[o * 64 + k2 * 2], W2[o * 64 + k2 * 2 + 1]);
    }
    __syncthreads();  // params + W tiles visible to all warps

    int r0 = wi * 16 + q, r1 = r0 + 8;
    bool ok0 = (r0 < rows_valid), ok1 = (r1 < rows_valid);

    // LN1 -> aY (packed fp16x2 A-fragments; also the residual source)
    uint32_t aY[16];
    {
        const float* x0 = g_x + (size_t)(b * SS + s0 + r0) * 64;
        const float* x1 = g_x + (size_t)(b * SS + s0 + r1) * 64;
        float v0[16], v1[16];
        float sm0 = 0.f, sq0 = 0.f, sm1 = 0.f, sq1 = 0.f;
#pragma unroll
        for (int nt = 0; nt < 8; nt++) {
            int c = nt * 8 + 2 * j;
            float2 t0 = ok0 ? *(const float2*)(x0 + c) : make_float2(0.f, 0.f);
            float2 t1 = ok1 ? *(const float2*)(x1 + c) : make_float2(0.f, 0.f);
            float a0 = t0.x + P[P_ATTN + c], a1 = t0.y + P[P_ATTN + c + 1];
            float a2 = t1.x + P[P_ATTN + c], a3 = t1.y + P[P_ATTN + c + 1];
            v0[2 * nt] = a0; v0[2 * nt + 1] = a1;
            v1[2 * nt] = a2; v1[2 * nt + 1] = a3;
            sm0 += a0 + a1; sq0 += a0 * a0 + a1 * a1;
            sm1 += a2 + a3; sq1 += a2 * a2 + a3 * a3;
        }
        sm0 += __shfl_xor_sync(0xffffffffu, sm0, 1);
        sq0 += __shfl_xor_sync(0xffffffffu, sq0, 1);
        sm1 += __shfl_xor_sync(0xffffffffu, sm1, 1);
        sq1 += __shfl_xor_sync(0xffffffffu, sq1, 1);
        sm0 += __shfl_xor_sync(0xffffffffu, sm0, 2);
        sq0 += __shfl_xor_sync(0xffffffffu, sq0, 2);
        sm1 += __shfl_xor_sync(0xffffffffu, sm1, 2);
        sq1 += __shfl_xor_sync(0xffffffffu, sq1, 2);
        float mu0 = sm0 * (1.0f / 64.0f);
        float rs0 = rsqrtf(sq0 * (1.0f / 64.0f) - mu0 * mu0 + EPS);
        float mu1 = sm1 * (1.0f / 64.0f);
        float rs1 = rsqrtf(sq1 * (1.0f / 64.0f) - mu1 * mu1 + EPS);
#pragma unroll
        for (int nt = 0; nt < 8; nt++) {
            int c = nt * 8 + 2 * j;
            float g0 = P[P_G1 + c], g1 = P[P_G1 + c + 1];
            float n0 = P[P_N1 + c], n1 = P[P_N1 + c + 1];
            float y0 = (v0[2 * nt] - mu0) * rs0 * g0 + n0;
            float y1 = (v0[2 * nt + 1] - mu0) * rs0 * g1 + n1;
            float y2 = (v1[2 * nt] - mu1) * rs1 * g0 + n0;
            float y3 = (v1[2 * nt + 1] - mu1) * rs1 * g1 + n1;
            // D-frag (row q / q+8, cols c..c+1) -> A-frag index mapping
            int idx = 4 * (nt >> 1) + (nt & 1) * 2;
            aY[idx] = pack_f16(y0, y1);       // row q
            aY[idx + 1] = pack_f16(y2, y3);   // row q+8
        }
    }

    // GEMM1 (A in regs, W1 in smem)
    float d1[8][4];
#pragma unroll
    for (int n = 0; n < 8; n++)
#pragma unroll
        for (int k = 0; k < 4; k++) d1[n][k] = 0.f;
    gemm_f16_regA(d1, aY, smb + SM_W1H, lane);

    // relu -> aH (packed fp16x2 A-fragments, in regs)
    uint32_t aH[16];
#pragma unroll
    for (int nt = 0; nt < 8; nt++) {
        int c = nt * 8 + 2 * j;
        float b1a = P[P_B1 + c], b1b = P[P_B1 + c + 1];
        float h0 = fmaxf(d1[nt][0] + b1a, 0.f);
        float h1 = fmaxf(d1[nt][1] + b1b, 0.f);
        float h2 = fmaxf(d1[nt][2] + b1a, 0.f);
        float h3 = fmaxf(d1[nt][3] + b1b, 0.f);
        int idx = 4 * (nt >> 1) + (nt & 1) * 2;
        aH[idx] = pack_f16(h0, h1);
        aH[idx + 1] = pack_f16(h2, h3);
    }

    // GEMM2 (A in regs, W2 in smem) — reuse d1 as accumulator
    float d2[8][4];
#pragma unroll
    for (int n = 0; n < 8; n++)
#pragma unroll
        for (int k = 0; k < 4; k++) d2[n][k] = 0.f;
    gemm_f16_regA(d2, aH, smb + SM_W2H, lane);

    // residual (from aY regs) + bias + LN2
    float v0[16], v1[16];
    {
        float sm0 = 0.f, sq0 = 0.f, sm1 = 0.f, sq1 = 0.f;
#pragma unroll
        for (int nt = 0; nt < 8; nt++) {
            int c = nt * 8 + 2 * j;
            int idx = 4 * (nt >> 1) + (nt & 1) * 2;
            float2 y01 = unpack_f16(aY[idx]);
            float2 y23 = unpack_f16(aY[idx + 1]);
            float b2a = P[P_B2 + c], b2b = P[P_B2 + c + 1];
            float a0 = d2[nt][0] + b2a + y01.x;
            float a1 = d2[nt][1] + b2b + y01.y;
            float a2 = d2[nt][2] + b2a + y23.x;
            float a3 = d2[nt][3] + b2b + y23.y;
            v0[2 * nt] = a0; v0[2 * nt + 1] = a1;
            v1[2 * nt] = a2; v1[2 * nt + 1] = a3;
            sm0 += a0 + a1; sq0 += a0 * a0 + a1 * a1;
            sm1 += a2 + a3; sq1 += a2 * a2 + a3 * a3;
        }
        sm0 += __shfl_xor_sync(0xffffffffu, sm0, 1);
        sq0 += __shfl_xor_sync(0xffffffffu, sq0, 1);
        sm1 += __shfl_xor_sync(0xffffffffu, sm1, 1);
        sq1 += __shfl_xor_sync(0xffffffffu, sq1, 1);
        sm0 += __shfl_xor_sync(0xffffffffu, sm0, 2);
        sq0 += __shfl_xor_sync(0xffffffffu, sq0, 2);
        sm1 += __shfl_xor_sync(0xffffffffu, sm1, 2);
        sq1 += __shfl_xor_sync(0xffffffffu, sq1, 2);
        float mu0 = sm0 * (1.0f / 64.0f);
        float rs0 = rsqrtf(sq0 * (1.0f / 64.0f) - mu0 * mu0 + EPS);
        float mu1 = sm1 * (1.0f / 64.0f);
        float rs1 = rsqrtf(sq1 * (1.0f / 64.0f) - mu1 * mu1 + EPS);
#pragma unroll
        for (int nt = 0; nt < 8; nt++) {
            int c = nt * 8 + 2 * j;
            float g0 = P[P_G2 + c], g1 = P[P_G2 + c + 1];
            float n0 = P[P_N2 + c], n1 = P[P_N2 + c + 1];
            v0[2 * nt] = (v0[2 * nt] - mu0) * rs0 * g0 + n0;
            v0[2 * nt + 1] = (v0[2 * nt + 1] - mu0) * rs0 * g1 + n1;
            v1[2 * nt] = (v1[2 * nt] - mu1) * rs1 * g0 + n0;
            v1[2 * nt + 1] = (v1[2 * nt + 1] - mu1) * rs1 * g1 + n1;
        }
    }

    if (l < NLAYERS - 1) {
        float* x0 = g_x + (size_t)(b * SS + s0 + r0) * 64;
        float* x1 = g_x + (size_t)(b * SS + s0 + r1) * 64;
#pragma unroll
        for (int nt = 0; nt < 8; nt++) {
            int c = nt * 8 + 2 * j;
            if (ok0) *(float2*)(x0 + c) = make_float2(v0[2 * nt], v0[2 * nt + 1]);
            if (ok1) *(float2*)(x1 + c) = make_float2(v1[2 * nt], v1[2 * nt + 1]);
        }
        float s[16];
#pragma unroll
        for (int i = 0; i < 16; i++)
            s[i] = (ok0 ? v0[i] : 0.f) + (ok1 ? v1[i] : 0.f);
#pragma unroll
        for (int i = 0; i < 16; i++) {
            s[i] += __shfl_xor_sync(0xffffffffu, s[i], 4);
            s[i] += __shfl_xor_sync(0xffffffffu, s[i], 8);
            s[i] += __shfl_xor_sync(0xffffffffu, s[i], 16);
        }
        if (q == 0) {
#pragma unroll
            for (int nt = 0; nt < 8; nt++) {
                int c = nt * 8 + 2 * j;
                atomicAdd(&P[P_SUM + c], s[2 * nt]);
                atomicAdd(&P[P_SUM + c + 1], s[2 * nt + 1]);
            }
        }
        __syncthreads();
        if (tid < 64)
            atomicAdd(&g_sums[(l + 1) * BB * DMODEL + b * DMODEL + tid],
                      P[P_SUM + tid]);
    } else {
        float p00 = 0.f, p10 = 0.f, p01 = 0.f, p11 = 0.f;
#pragma unroll
        for (int nt = 0; nt < 8; nt++) {
            int c = nt * 8 + 2 * j;
            float w0 = P[P_OW + c], w1 = P[P_OW + c + 1];
            float u0 = P[P_OW + 64 + c], u1 = P[P_OW + 64 + c + 1];
            p00 = fmaf(v0[2 * nt], w0, fmaf(v0[2 * nt + 1], w1, p00));
            p10 = fmaf(v0[2 * nt], u0, fmaf(v0[2 * nt + 1], u1, p10));
            p01 = fmaf(v1[2 * nt], w0, fmaf(v1[2 * nt + 1], w1, p01));
            p11 = fmaf(v1[2 * nt], u0, fmaf(v1[2 * nt + 1], u1, p11));
        }
        p00 += __shfl_xor_sync(0xffffffffu, p00, 1);
        p10 += __shfl_xor_sync(0xffffffffu, p10, 1);
        p01 += __shfl_xor_sync(0xffffffffu, p01, 1);
        p11 += __shfl_xor_sync(0xffffffffu, p11, 1);
        p00 += __shfl_xor_sync(0xffffffffu, p00, 2);
        p10 += __shfl_xor_sync(0xffffffffu, p10, 2);
        p01 += __shfl_xor_sync(0xffffffffu, p01, 2);
        p11 += __shfl_xor_sync(0xffffffffu, p11, 2);
        if (j == 0) {
            if (ok0)
                *(float2*)(out + (size_t)(b * SS + s0 + r0) * 2) =
                    make_float2(p00 + P[P_OB], p10 + P[P_OB + 1]);
            if (ok1)
                *(float2*)(out + (size_t)(b * SS + s0 + r1) * 2) =
                    make_float2(p01 + P[P_OB], p11 + P[P_OB + 1]);
        }
    }
}

// ---------------------------------------------------------------------------
extern "C" void kernel_launch(void* const* d_in, const int* in_sizes, int n_in,
                              void* d_out, int out_size) {
    const int*   tokens = (const int*)d_in[0];
    const float* emb    = (const float*)d_in[1];
    const float* lin_w  = (const float*)d_in[2];
    const float* lin_b  = (const float*)d_in[3];
    const float* ff1_w  = (const float*)d_in[4];
    const float* ff1_b  = (const float*)d_in[5];
    const float* ff2_w  = (const float*)d_in[6];
    const float* ff2_b  = (const float*)d_in[7];
    const float* n1g    = (const float*)d_in[8];
    const float* n1b    = (const float*)d_in[9];
    const float* n2g    = (const float*)d_in[10];
    const float* n2b    = (const float*)d_in[11];
    const float* ow     = (const float*)d_in[12];
    const float* ob     = (const float*)d_in[13];
    float* out = (float*)d_out;

    cudaFuncSetAttribute(k_layer12, cudaFuncAttributeMaxDynamicSharedMemorySize,
                         SM_TOTAL);

    k_init<<<128, 256>>>();
    k_embed<<<dim3(8, BB), 256>>>(tokens, emb);
    for (int l = 0; l < NLAYERS; l++) {
        k_attn<<<BB, 64>>>(lin_w, lin_b, l);
        k_layer12<<<dim3(16, BB), 128, SM_TOTAL>>>(ff1_w, ff1_b, ff2_w, ff2_b,
                                                   n1g, n1b, n2g, n2b, ow, ob,
                                                   out, l);
    }
}

// round 17
// speedup vs baseline: 2.2997x; 1.0873x over previous
#include <cuda_runtime.h>
#include <cuda_bf16.h>
#include <cuda_fp16.h>
#include <math.h>
#include <stdint.h>

#define VOCAB 32000
#define DMODEL 64
#define NLAYERS 4
#define BB 512
#define SS 1000
#define EPS 1e-5f

__device__ float g_x[BB * SS * DMODEL];
__device__ float g_pe[SS * DMODEL];
__device__ float g_sums[NLAYERS * BB * DMODEL];
__device__ float g_attn[BB * DMODEL];

// ---------------------------------------------------------------------------
__device__ __forceinline__ uint32_t smem_u32(const void* p) {
    uint32_t a;
    asm("{ .reg .u64 t; cvta.to.shared.u64 t, %1; cvt.u32.u64 %0, t; }"
        : "=r"(a) : "l"(p));
    return a;
}

#define LDSM4(r0, r1, r2, r3, addr)                                         \
    asm volatile("ldmatrix.sync.aligned.m8n8.x4.shared.b16 {%0,%1,%2,%3}, [%4];" \
                 : "=r"(r0), "=r"(r1), "=r"(r2), "=r"(r3) : "r"(addr))

#define MMA_F16(d, a0, a1, a2, a3, b0, b1)                                  \
    asm volatile("mma.sync.aligned.m16n8k16.row.col.f32.f16.f16.f32 "       \
                 "{%0,%1,%2,%3}, {%4,%5,%6,%7}, {%8,%9}, {%0,%1,%2,%3};"    \
                 : "+f"((d)[0]), "+f"((d)[1]), "+f"((d)[2]), "+f"((d)[3])   \
                 : "r"(a0), "r"(a1), "r"(a2), "r"(a3), "r"(b0), "r"(b1))

__device__ __forceinline__ uint32_t pack_f16(float a, float b) {
    __half2 t = __floats2half2_rn(a, b);
    return *reinterpret_cast<uint32_t*>(&t);
}
__device__ __forceinline__ float2 unpack_f16(uint32_t u) {
    __half2 h = *reinterpret_cast<__half2*>(&u);
    return make_float2(__half2float(__low2half(h)), __half2float(__high2half(h)));
}

// swizzled byte offset inside a (rows x 128B) tile: row r, 16B-chunk c (0..7)
__device__ __forceinline__ uint32_t tile_off(uint32_t r, uint32_t c) {
    return r * 128 + ((c ^ (r & 7u)) << 4);
}

// ---------------------------------------------------------------------------
__global__ void k_init() {
    int i = blockIdx.x * blockDim.x + threadIdx.x;
    int n = blockDim.x * gridDim.x;
    for (int idx = i; idx < NLAYERS * BB * DMODEL; idx += n) g_sums[idx] = 0.0f;
    const float c = -0.14391156634610842f;
    for (int idx = i; idx < SS * DMODEL; idx += n) {
        int s = idx >> 6;
        int j = idx & 63;
        float div = expf(c * (float)(j & ~1));
        float ang = (float)s * div;
        g_pe[idx] = (j & 1) ? cosf(ang) : sinf(ang);
    }
}

__global__ __launch_bounds__(256) void k_embed(const int* __restrict__ toks,
                                               const float* __restrict__ emb) {
    int b = blockIdx.y;
    int s0 = blockIdx.x * 128;
    int w = threadIdx.x >> 5, lane = threadIdx.x & 31;
    float acc0 = 0.f, acc1 = 0.f;
    for (int r = w; r < 128; r += 8) {
        int s = s0 + r;
        if (s >= SS) break;
        int tok = toks[b * SS + s];
        float v0 = emb[tok * DMODEL + lane] * 8.0f + g_pe[s * DMODEL + lane];
        float v1 = emb[tok * DMODEL + 32 + lane] * 8.0f + g_pe[s * DMODEL + 32 + lane];
        int row = b * SS + s;
        g_x[row * DMODEL + lane] = v0;
        g_x[row * DMODEL + 32 + lane] = v1;
        acc0 += v0;
        acc1 += v1;
    }
    atomicAdd(&g_sums[0 * BB * DMODEL + b * DMODEL + lane], acc0);
    atomicAdd(&g_sums[0 * BB * DMODEL + b * DMODEL + 32 + lane], acc1);
}

__global__ void k_attn(const float* __restrict__ lin_w,
                       const float* __restrict__ lin_b, int l) {
    __shared__ float avg[DMODEL];
    int b = blockIdx.x, o = threadIdx.x;
    avg[o] = g_sums[l * BB * DMODEL + b * DMODEL + o] * (1.0f / (float)SS);
    __syncthreads();
    const float* W = lin_w + l * DMODEL * DMODEL + o * DMODEL;
    float a = lin_b[l * DMODEL + o];
#pragma unroll
    for (int k = 0; k < DMODEL; k++) a = fmaf(avg[k], W[k], a);
    g_attn[b * DMODEL + o] = a;
}

// ---------------------------------------------------------------------------
// k_layer13: R16 register-A structure + ALL scalar param/weight accesses
// vectorized to float2 (halves epilogue/prologue L1 instruction count).
// Numerics identical to R16.
// ---------------------------------------------------------------------------
#define P_ATTN 0
#define P_B1 64
#define P_B2 128
#define P_G1 192
#define P_N1 256
#define P_G2 320
#define P_N2 384
#define P_OW 448
#define P_OB 576
#define P_SUM 640

#define SM_W1H 2816
#define SM_W2H (SM_W1H + 8192)
#define SM_TOTAL (SM_W2H + 8192)

// fp16 GEMM with register A: D += A(frags) @ W(smem, single fp16)^T, K=64
__device__ __forceinline__ void gemm_f16_regA(float (&d)[8][4],
                                              const uint32_t (&a)[16],
                                              uint32_t wt, int lane) {
    uint32_t bg = (uint32_t)(lane >> 3);
    uint32_t wr = ((bg & 2u) << 2) | (lane & 7u);
    uint32_t wc = bg & 1u;
#pragma unroll
    for (int ntp = 0; ntp < 4; ntp++)
#pragma unroll
        for (int kt = 0; kt < 4; kt++) {
            uint32_t off = tile_off(ntp * 16 + wr, kt * 2 + wc);
            uint32_t h0, h1, h2, h3;
            LDSM4(h0, h1, h2, h3, wt + off);
            MMA_F16(d[2 * ntp], a[4 * kt], a[4 * kt + 1], a[4 * kt + 2],
                    a[4 * kt + 3], h0, h1);
            MMA_F16(d[2 * ntp + 1], a[4 * kt], a[4 * kt + 1], a[4 * kt + 2],
                    a[4 * kt + 3], h2, h3);
        }
}

__global__ __launch_bounds__(128, 5)
void k_layer13(const float* __restrict__ ff1_w, const float* __restrict__ ff1_b,
               const float* __restrict__ ff2_w, const float* __restrict__ ff2_b,
               const float* __restrict__ n1_g, const float* __restrict__ n1_b,
               const float* __restrict__ n2_g, const float* __restrict__ n2_b,
               const float* __restrict__ out_w, const float* __restrict__ out_b,
               float* __restrict__ out, int l) {
    extern __shared__ char sm[];
    float* P = (float*)sm;
    uint32_t smb = smem_u32(sm);

    int tid = threadIdx.x;
    int wi = tid >> 5;
    int lane = tid & 31;
    int q = lane >> 2, j = lane & 3;
    int b = blockIdx.y;
    int s0 = blockIdx.x * 64;
    int rows_valid = SS - s0;
    if (rows_valid > 64) rows_valid = 64;

    // params
    if (tid < 64) {
        P[P_ATTN + tid] = g_attn[b * DMODEL + tid];
        P[P_B1 + tid] = ff1_b[l * DMODEL + tid];
        P[P_B2 + tid] = ff2_b[l * DMODEL + tid];
        P[P_G1 + tid] = n1_g[l * DMODEL + tid];
        P[P_N1 + tid] = n1_b[l * DMODEL + tid];
        P[P_G2 + tid] = n2_g[l * DMODEL + tid];
        P[P_N2 + tid] = n2_b[l * DMODEL + tid];
        P[P_SUM + tid] = 0.0f;
    }
    P[P_OW + tid] = out_w[tid];
    if (tid < 2) P[P_OB + tid] = out_b[tid];

    // W1 + W2 (single fp16, swizzled), float2 gmem loads
    const float2* W1v = (const float2*)(ff1_w + l * 4096);
    const float2* W2v = (const float2*)(ff2_w + l * 4096);
#pragma unroll
    for (int it = 0; it < 16; it++) {
        int i = tid + it * 128;
        int o = i >> 5, k2 = i & 31;
        uint32_t off = (uint32_t)(o * 128) +
                       ((((uint32_t)(k2 >> 2)) ^ (o & 7u)) << 4) + (k2 & 3) * 4;
        float2 w1 = W1v[o * 32 + k2];
        float2 w2 = W2v[o * 32 + k2];
        *(uint32_t*)(sm + SM_W1H + off) = pack_f16(w1.x, w1.y);
        *(uint32_t*)(sm + SM_W2H + off) = pack_f16(w2.x, w2.y);
    }
    __syncthreads();  // params + W tiles visible to all warps

    int r0 = wi * 16 + q, r1 = r0 + 8;
    bool ok0 = (r0 < rows_valid), ok1 = (r1 < rows_valid);

    // LN1 -> aY (packed fp16x2 A-fragments; also the residual source)
    uint32_t aY[16];
    {
        const float* x0 = g_x + (size_t)(b * SS + s0 + r0) * 64;
        const float* x1 = g_x + (size_t)(b * SS + s0 + r1) * 64;
        float v0[16], v1[16];
        float sm0 = 0.f, sq0 = 0.f, sm1 = 0.f, sq1 = 0.f;
#pragma unroll
        for (int nt = 0; nt < 8; nt++) {
            int c = nt * 8 + 2 * j;
            float2 pa = *(const float2*)&P[P_ATTN + c];
            float2 t0 = ok0 ? *(const float2*)(x0 + c) : make_float2(0.f, 0.f);
            float2 t1 = ok1 ? *(const float2*)(x1 + c) : make_float2(0.f, 0.f);
            float a0 = t0.x + pa.x, a1 = t0.y + pa.y;
            float a2 = t1.x + pa.x, a3 = t1.y + pa.y;
            v0[2 * nt] = a0; v0[2 * nt + 1] = a1;
            v1[2 * nt] = a2; v1[2 * nt + 1] = a3;
            sm0 += a0 + a1; sq0 += a0 * a0 + a1 * a1;
            sm1 += a2 + a3; sq1 += a2 * a2 + a3 * a3;
        }
        sm0 += __shfl_xor_sync(0xffffffffu, sm0, 1);
        sq0 += __shfl_xor_sync(0xffffffffu, sq0, 1);
        sm1 += __shfl_xor_sync(0xffffffffu, sm1, 1);
        sq1 += __shfl_xor_sync(0xffffffffu, sq1, 1);
        sm0 += __shfl_xor_sync(0xffffffffu, sm0, 2);
        sq0 += __shfl_xor_sync(0xffffffffu, sq0, 2);
        sm1 += __shfl_xor_sync(0xffffffffu, sm1, 2);
        sq1 += __shfl_xor_sync(0xffffffffu, sq1, 2);
        float mu0 = sm0 * (1.0f / 64.0f);
        float rs0 = rsqrtf(sq0 * (1.0f / 64.0f) - mu0 * mu0 + EPS);
        float mu1 = sm1 * (1.0f / 64.0f);
        float rs1 = rsqrtf(sq1 * (1.0f / 64.0f) - mu1 * mu1 + EPS);
#pragma unroll
        for (int nt = 0; nt < 8; nt++) {
            int c = nt * 8 + 2 * j;
            float2 g = *(const float2*)&P[P_G1 + c];
            float2 n = *(const float2*)&P[P_N1 + c];
            float y0 = (v0[2 * nt] - mu0) * rs0 * g.x + n.x;
            float y1 = (v0[2 * nt + 1] - mu0) * rs0 * g.y + n.y;
            float y2 = (v1[2 * nt] - mu1) * rs1 * g.x + n.x;
            float y3 = (v1[2 * nt + 1] - mu1) * rs1 * g.y + n.y;
            int idx = 4 * (nt >> 1) + (nt & 1) * 2;
            aY[idx] = pack_f16(y0, y1);       // row q
            aY[idx + 1] = pack_f16(y2, y3);   // row q+8
        }
    }

    // GEMM1 (A in regs, W1 in smem)
    float d1[8][4];
#pragma unroll
    for (int n = 0; n < 8; n++)
#pragma unroll
        for (int k = 0; k < 4; k++) d1[n][k] = 0.f;
    gemm_f16_regA(d1, aY, smb + SM_W1H, lane);

    // relu -> aH (packed fp16x2 A-fragments, in regs)
    uint32_t aH[16];
#pragma unroll
    for (int nt = 0; nt < 8; nt++) {
        int c = nt * 8 + 2 * j;
        float2 b1 = *(const float2*)&P[P_B1 + c];
        float h0 = fmaxf(d1[nt][0] + b1.x, 0.f);
        float h1 = fmaxf(d1[nt][1] + b1.y, 0.f);
        float h2 = fmaxf(d1[nt][2] + b1.x, 0.f);
        float h3 = fmaxf(d1[nt][3] + b1.y, 0.f);
        int idx = 4 * (nt >> 1) + (nt & 1) * 2;
        aH[idx] = pack_f16(h0, h1);
        aH[idx + 1] = pack_f16(h2, h3);
    }

    // GEMM2 (A in regs, W2 in smem)
    float d2[8][4];
#pragma unroll
    for (int n = 0; n < 8; n++)
#pragma unroll
        for (int k = 0; k < 4; k++) d2[n][k] = 0.f;
    gemm_f16_regA(d2, aH, smb + SM_W2H, lane);

    // residual (from aY regs) + bias + LN2
    float v0[16], v1[16];
    {
        float sm0 = 0.f, sq0 = 0.f, sm1 = 0.f, sq1 = 0.f;
#pragma unroll
        for (int nt = 0; nt < 8; nt++) {
            int c = nt * 8 + 2 * j;
            int idx = 4 * (nt >> 1) + (nt & 1) * 2;
            float2 y01 = unpack_f16(aY[idx]);
            float2 y23 = unpack_f16(aY[idx + 1]);
            float2 b2 = *(const float2*)&P[P_B2 + c];
            float a0 = d2[nt][0] + b2.x + y01.x;
            float a1 = d2[nt][1] + b2.y + y01.y;
            float a2 = d2[nt][2] + b2.x + y23.x;
            float a3 = d2[nt][3] + b2.y + y23.y;
            v0[2 * nt] = a0; v0[2 * nt + 1] = a1;
            v1[2 * nt] = a2; v1[2 * nt + 1] = a3;
            sm0 += a0 + a1; sq0 += a0 * a0 + a1 * a1;
            sm1 += a2 + a3; sq1 += a2 * a2 + a3 * a3;
        }
        sm0 += __shfl_xor_sync(0xffffffffu, sm0, 1);
        sq0 += __shfl_xor_sync(0xffffffffu, sq0, 1);
        sm1 += __shfl_xor_sync(0xffffffffu, sm1, 1);
        sq1 += __shfl_xor_sync(0xffffffffu, sq1, 1);
        sm0 += __shfl_xor_sync(0xffffffffu, sm0, 2);
        sq0 += __shfl_xor_sync(0xffffffffu, sq0, 2);
        sm1 += __shfl_xor_sync(0xffffffffu, sm1, 2);
        sq1 += __shfl_xor_sync(0xffffffffu, sq1, 2);
        float mu0 = sm0 * (1.0f / 64.0f);
        float rs0 = rsqrtf(sq0 * (1.0f / 64.0f) - mu0 * mu0 + EPS);
        float mu1 = sm1 * (1.0f / 64.0f);
        float rs1 = rsqrtf(sq1 * (1.0f / 64.0f) - mu1 * mu1 + EPS);
#pragma unroll
        for (int nt = 0; nt < 8; nt++) {
            int c = nt * 8 + 2 * j;
            float2 g = *(const float2*)&P[P_G2 + c];
            float2 n = *(const float2*)&P[P_N2 + c];
            v0[2 * nt] = (v0[2 * nt] - mu0) * rs0 * g.x + n.x;
            v0[2 * nt + 1] = (v0[2 * nt + 1] - mu0) * rs0 * g.y + n.y;
            v1[2 * nt] = (v1[2 * nt] - mu1) * rs1 * g.x + n.x;
            v1[2 * nt + 1] = (v1[2 * nt + 1] - mu1) * rs1 * g.y + n.y;
        }
    }

    if (l < NLAYERS - 1) {
        float* x0 = g_x + (size_t)(b * SS + s0 + r0) * 64;
        float* x1 = g_x + (size_t)(b * SS + s0 + r1) * 64;
#pragma unroll
        for (int nt = 0; nt < 8; nt++) {
            int c = nt * 8 + 2 * j;
            if (ok0) *(float2*)(x0 + c) = make_float2(v0[2 * nt], v0[2 * nt + 1]);
            if (ok1) *(float2*)(x1 + c) = make_float2(v1[2 * nt], v1[2 * nt + 1]);
        }
        float s[16];
#pragma unroll
        for (int i = 0; i < 16; i++)
            s[i] = (ok0 ? v0[i] : 0.f) + (ok1 ? v1[i] : 0.f);
#pragma unroll
        for (int i = 0; i < 16; i++) {
            s[i] += __shfl_xor_sync(0xffffffffu, s[i], 4);
            s[i] += __shfl_xor_sync(0xffffffffu, s[i], 8);
            s[i] += __shfl_xor_sync(0xffffffffu, s[i], 16);
        }
        if (q == 0) {
#pragma unroll
            for (int nt = 0; nt < 8; nt++) {
                int c = nt * 8 + 2 * j;
                atomicAdd(&P[P_SUM + c], s[2 * nt]);
                atomicAdd(&P[P_SUM + c + 1], s[2 * nt + 1]);
            }
        }
        __syncthreads();
        if (tid < 64)
            atomicAdd(&g_sums[(l + 1) * BB * DMODEL + b * DMODEL + tid],
                      P[P_SUM + tid]);
    } else {
        float p00 = 0.f, p10 = 0.f, p01 = 0.f, p11 = 0.f;
#pragma unroll
        for (int nt = 0; nt < 8; nt++) {
            int c = nt * 8 + 2 * j;
            float2 w = *(const float2*)&P[P_OW + c];
            float2 u = *(const float2*)&P[P_OW + 64 + c];
            p00 = fmaf(v0[2 * nt], w.x, fmaf(v0[2 * nt + 1], w.y, p00));
            p10 = fmaf(v0[2 * nt], u.x, fmaf(v0[2 * nt + 1], u.y, p10));
            p01 = fmaf(v1[2 * nt], w.x, fmaf(v1[2 * nt + 1], w.y, p01));
            p11 = fmaf(v1[2 * nt], u.x, fmaf(v1[2 * nt + 1], u.y, p11));
        }
        p00 += __shfl_xor_sync(0xffffffffu, p00, 1);
        p10 += __shfl_xor_sync(0xffffffffu, p10, 1);
        p01 += __shfl_xor_sync(0xffffffffu, p01, 1);
        p11 += __shfl_xor_sync(0xffffffffu, p11, 1);
        p00 += __shfl_xor_sync(0xffffffffu, p00, 2);
        p10 += __shfl_xor_sync(0xffffffffu, p10, 2);
        p01 += __shfl_xor_sync(0xffffffffu, p01, 2);
        p11 += __shfl_xor_sync(0xffffffffu, p11, 2);
        if (j == 0) {
            if (ok0)
                *(float2*)(out + (size_t)(b * SS + s0 + r0) * 2) =
                    make_float2(p00 + P[P_OB], p10 + P[P_OB + 1]);
            if (ok1)
                *(float2*)(out + (size_t)(b * SS + s0 + r1) * 2) =
                    make_float2(p01 + P[P_OB], p11 + P[P_OB + 1]);
        }
    }
}

// ---------------------------------------------------------------------------
extern "C" void kernel_launch(void* const* d_in, const int* in_sizes, int n_in,
                              void* d_out, int out_size) {
    const int*   tokens = (const int*)d_in[0];
    const float* emb    = (const float*)d_in[1];
    const float* lin_w  = (const float*)d_in[2];
    const float* lin_b  = (const float*)d_in[3];
    const float* ff1_w  = (const float*)d_in[4];
    const float* ff1_b  = (const float*)d_in[5];
    const float* ff2_w  = (const float*)d_in[6];
    const float* ff2_b  = (const float*)d_in[7];
    const float* n1g    = (const float*)d_in[8];
    const float* n1b    = (const float*)d_in[9];
    const float* n2g    = (const float*)d_in[10];
    const float* n2b    = (const float*)d_in[11];
    const float* ow     = (const float*)d_in[12];
    const float* ob     = (const float*)d_in[13];
    float* out = (float*)d_out;

    cudaFuncSetAttribute(k_layer13, cudaFuncAttributeMaxDynamicSharedMemorySize,
                         SM_TOTAL);

    k_init<<<128, 256>>>();
    k_embed<<<dim3(8, BB), 256>>>(tokens, emb);
    for (int l = 0; l < NLAYERS; l++) {
        k_attn<<<BB, 64>>>(lin_w, lin_b, l);
        k_layer13<<<dim3(16, BB), 128, SM_TOTAL>>>(ff1_w, ff1_b, ff2_w, ff2_b,
                                                   n1g, n1b, n2g, n2b, ow, ob,
                                                   out, l);
    }
}